// round 12
// baseline (speedup 1.0000x reference)
#include <cuda_runtime.h>
#include <cuda_fp16.h>
#include <cuda.h>
#include <nvrtc.h>
#include <dlfcn.h>
#include <cstdio>
#include <cstdlib>
#include <cstring>
#include <cstdint>

// ============================================================================
// Embedded tcgen05 kernel (NVRTC, --gpu-architecture=sm_103a).
// Single 256-thread pipeline, TWO tile slots in flight (A/B interleaved):
// slot A's epilogue hides slot B's MMA chain and vice versa.
// probe=1 keeps the identical instruction structure with all global memory
// accesses guarded out (ctor-time validation on null pointers).
// ============================================================================
static const char* TC_SRC = R"___(
typedef unsigned int u32;
typedef unsigned long long u64;

#define SW0   1024u
#define SW1   17408u
#define SW2   50176u
#define SW3   82944u
#define SW4   115712u
#define SW5   148480u
#define SACT0 152576u
#define SACT1 185344u
#define IDESC_N128 ((1u<<4) | (16u<<17) | (8u<<24))
#define IDESC_N16  ((1u<<4) | ( 2u<<17) | (8u<<24))

__device__ __forceinline__ u32 swz(u32 o) { return o ^ ((o >> 3) & 0x70u); }

__device__ __forceinline__ u64 mdesc(u32 addr) {
    return ((u64)2 << 61) | ((u64)1 << 46) | ((u64)64 << 32) | ((u64)1 << 16)
         | ((u64)(addr >> 4) & 0x3FFFu);
}
__device__ __forceinline__ void st_h(u32 a, float v) {
    asm volatile("{.reg .b16 h; cvt.rn.f16.f32 h, %1; st.shared.b16 [%0], h;}"
                 :: "r"(a), "f"(v) : "memory");
}
__device__ __forceinline__ u32 rpack(float a, float b) {
    u32 r;
    asm("cvt.rn.f16x2.f32 %0, %1, %2;" : "=r"(r) : "f"(b), "f"(a));
    asm("max.f16x2 %0, %0, %1;" : "+r"(r) : "r"(0u));
    return r;
}
__device__ __forceinline__ void tc_mma(u32 d, u64 a, u64 b, u32 id, u32 en) {
    asm volatile("{.reg .pred p; setp.ne.u32 p, %4, 0;\n\t"
        "tcgen05.mma.cta_group::1.kind::f16 [%0], %1, %2, %3, {%5,%5,%5,%5}, p;}"
        :: "r"(d), "l"(a), "l"(b), "r"(id), "r"(en), "r"(0u) : "memory");
}
__device__ __forceinline__ bool elect1() {
    u32 p;
    asm volatile("{.reg .pred p; elect.sync _|p, 0xFFFFFFFF; selp.b32 %0,1,0,p;}"
                 : "=r"(p));
    return p != 0;
}
#define MBAR_INIT(mb, c) \
    asm volatile("mbarrier.init.shared.b64 [%0], %1;" \
        :: "r"((u32)(mb)), "r"((u32)(c)) : "memory")
__device__ __forceinline__ void mbar_wait_b(u32 mb, u32 par) {
    for (int i = 0; i < 4096; i++) {
        u32 d;
        asm volatile("{.reg .pred p;\n\t"
            "mbarrier.try_wait.parity.acquire.cta.shared::cta.b64 p, [%1], %2, 0x989680;\n\t"
            "selp.b32 %0,1,0,p;}" : "=r"(d) : "r"(mb), "r"(par) : "memory");
        if (d) return;
    }
}
#define LDTM_X32(r, a) \
    asm volatile("tcgen05.ld.sync.aligned.32x32b.x32.b32 " \
        "{%0,%1,%2,%3,%4,%5,%6,%7,%8,%9,%10,%11,%12,%13,%14,%15," \
        "%16,%17,%18,%19,%20,%21,%22,%23,%24,%25,%26,%27,%28,%29,%30,%31}, [%32];" \
        : "=r"((r)[0]),"=r"((r)[1]),"=r"((r)[2]),"=r"((r)[3]), \
          "=r"((r)[4]),"=r"((r)[5]),"=r"((r)[6]),"=r"((r)[7]), \
          "=r"((r)[8]),"=r"((r)[9]),"=r"((r)[10]),"=r"((r)[11]), \
          "=r"((r)[12]),"=r"((r)[13]),"=r"((r)[14]),"=r"((r)[15]), \
          "=r"((r)[16]),"=r"((r)[17]),"=r"((r)[18]),"=r"((r)[19]), \
          "=r"((r)[20]),"=r"((r)[21]),"=r"((r)[22]),"=r"((r)[23]), \
          "=r"((r)[24]),"=r"((r)[25]),"=r"((r)[26]),"=r"((r)[27]), \
          "=r"((r)[28]),"=r"((r)[29]),"=r"((r)[30]),"=r"((r)[31]) \
        : "r"(a))
#define LDTM_X16(r, a) \
    asm volatile("tcgen05.ld.sync.aligned.32x32b.x16.b32 " \
        "{%0,%1,%2,%3,%4,%5,%6,%7,%8,%9,%10,%11,%12,%13,%14,%15}, [%16];" \
        : "=r"((r)[0]),"=r"((r)[1]),"=r"((r)[2]),"=r"((r)[3]), \
          "=r"((r)[4]),"=r"((r)[5]),"=r"((r)[6]),"=r"((r)[7]), \
          "=r"((r)[8]),"=r"((r)[9]),"=r"((r)[10]),"=r"((r)[11]), \
          "=r"((r)[12]),"=r"((r)[13]),"=r"((r)[14]),"=r"((r)[15]) \
        : "r"(a))

extern "C" __global__ void __launch_bounds__(256, 1)
mlp_tc(const float* x, const float* gW0, const float* gW1, const float* gW2,
       const float* gW3, const float* gW4, const float* gW5,
       const float* bias, float* out, int grid, int ntiles, int probe)
{
    extern __shared__ char smem[];
    u32 sb;
    asm("{.reg .u64 t; cvta.to.shared.u64 t, %1; cvt.u32.u64 %0, t;}"
        : "=r"(sb) : "l"(smem));
    const int tid = threadIdx.x, wid = tid >> 5, lane = tid & 31;
    const int sub = wid & 3;
    const int half = wid >> 2;
    const int myrow = sub * 32 + lane;

    if (wid == 0) {
        asm volatile("tcgen05.alloc.cta_group::1.sync.aligned.shared::cta.b32 [%0], %1;"
                     :: "r"(sb), "r"(512u) : "memory");
        asm volatile("tcgen05.relinquish_alloc_permit.cta_group::1.sync.aligned;");
    }
    if (tid == 0) { MBAR_INIT(sb + 8, 1); MBAR_INIT(sb + 16, 1); }

    {
        const float* gws[4] = {gW1, gW2, gW3, gW4};
        const u32 so[4] = {SW1, SW2, SW3, SW4};
        for (int w = 0; w < 4; w++)
            for (int i = tid; i < 128 * 128; i += 256) {
                int k = i >> 7, n = i & 127;
                u32 off = (u32)(k >> 6) * 16384u + (u32)n * 128u + (u32)(k & 63) * 2u;
                float v = probe ? 0.03f : gws[w][i];
                st_h(sb + so[w] + swz(off), v);
            }
    }
    for (int i = tid; i < 64 * 128; i += 256) {
        int k = i >> 7, n = i & 127;
        u32 off = (u32)n * 128u + (u32)k * 2u;
        float v = probe ? 0.02f : gW0[i];
        st_h(sb + SW0 + swz(off), v);
    }
    for (int i = tid; i < 128 * 16; i += 256) {
        int k = i >> 4, n = i & 15;
        u32 off = (u32)(k >> 6) * 2048u + (u32)n * 128u + (u32)(k & 63) * 2u;
        float v = probe ? 0.01f : gW5[i];
        st_h(sb + SW5 + swz(off), v);
    }
    float bz[16];
    for (int i = 0; i < 16; i++) bz[i] = probe ? 0.0f : bias[i];

    asm volatile("fence.proxy.async.shared::cta;" ::: "memory");
    __syncthreads();
    u32 tmem;
    asm volatile("ld.shared.b32 %0, [%1];" : "=r"(tmem) : "r"(sb));

    const u32 ACT[2]  = {SACT0, SACT1};
    const u32 WB[6]   = {SW0, SW1, SW2, SW3, SW4, SW5};
    const bool leader = (wid == 0);
    u32 ph[2] = {0u, 0u};

    for (int t0 = blockIdx.x * 2; t0 < ntiles; t0 += 2 * grid) {
        #pragma unroll
        for (int s = 0; s < 2; s++) {
            const float* xg = x + (u64)(t0 + s) * 128u * 64u;
            #pragma unroll
            for (int it = 0; it < 8; it++) {
                int idx = tid + it * 256;
                int r = idx >> 4, c4 = idx & 15;
                float vx, vy, vz, vw;
                if (probe) {
                    vx = (float)(idx & 7) * 0.05f; vy = 0.2f; vz = -0.1f; vw = 0.15f;
                } else {
                    asm("ld.global.nc.v4.f32 {%0,%1,%2,%3}, [%4];"
                        : "=f"(vx), "=f"(vy), "=f"(vz), "=f"(vw)
                        : "l"(xg + 4 * idx));
                }
                u32 p0, p1;
                asm("cvt.rn.f16x2.f32 %0, %1, %2;" : "=r"(p0) : "f"(vy), "f"(vx));
                asm("cvt.rn.f16x2.f32 %0, %1, %2;" : "=r"(p1) : "f"(vw), "f"(vz));
                u32 a = sb + ACT[s] + swz((u32)r * 128u + (u32)c4 * 8u);
                asm volatile("st.shared.v2.b32 [%0], {%1,%2};"
                             :: "r"(a), "r"(p0), "r"(p1) : "memory");
            }
        }
        asm volatile("fence.proxy.async.shared::cta;" ::: "memory");
        __syncthreads();

        if (leader && elect1()) {
            #pragma unroll
            for (int s = 0; s < 2; s++) {
                u64 ad = mdesc(sb + ACT[s]);
                u64 bd = mdesc(sb + SW0);
                for (int k = 0; k < 4; k++)
                    tc_mma(tmem + (u32)s * 128u, ad + (u32)k * 2u, bd + (u32)k * 2u,
                           IDESC_N128, (u32)(k > 0));
                asm volatile(
                    "tcgen05.commit.cta_group::1.mbarrier::arrive::one.shared::cluster.b64 [%0];"
                    :: "r"(sb + 8u + 8u * (u32)s) : "memory");
            }
        }

        for (int l = 1; l <= 5; l++) {
            const u32 idesc = (l == 5) ? IDESC_N16 : IDESC_N128;
            const u32 bstr  = (l == 5) ? 128u : 1024u;
            #pragma unroll
            for (int s = 0; s < 2; s++) {
                const u32 mbar  = sb + 8u + 8u * (u32)s;
                const u32 d_hid = tmem + (u32)s * 128u;
                mbar_wait_b(mbar, ph[s]);
                ph[s] ^= 1;
                asm volatile("tcgen05.fence::after_thread_sync;" ::: "memory");

                u32 r0[32], r1[32];
                LDTM_X32(r0, d_hid + (u32)half * 64u);
                LDTM_X32(r1, d_hid + (u32)half * 64u + 32u);
                asm volatile("tcgen05.wait::ld.sync.aligned;" ::: "memory");
                u32 rowb = ACT[s] + (u32)half * 16384u + (u32)myrow * 128u;
                #pragma unroll
                for (int i = 0; i < 16; i++) {
                    u32 pk = rpack(__uint_as_float(r0[2 * i]),
                                   __uint_as_float(r0[2 * i + 1]));
                    asm volatile("st.shared.b32 [%0], %1;"
                        :: "r"(sb + swz(rowb + (u32)(2 * i) * 2u)), "r"(pk)
                        : "memory");
                }
                #pragma unroll
                for (int i = 0; i < 16; i++) {
                    u32 pk = rpack(__uint_as_float(r1[2 * i]),
                                   __uint_as_float(r1[2 * i + 1]));
                    asm volatile("st.shared.b32 [%0], %1;"
                        :: "r"(sb + swz(rowb + (u32)(32 + 2 * i) * 2u)), "r"(pk)
                        : "memory");
                }
                asm volatile("tcgen05.fence::before_thread_sync;" ::: "memory");
                asm volatile("fence.proxy.async.shared::cta;" ::: "memory");
                __syncthreads();

                if (leader && elect1()) {
                    u64 ad = mdesc(sb + ACT[s]);
                    u64 bd = mdesc(sb + WB[l]);
                    for (int k = 0; k < 8; k++) {
                        u32 ao = (u32)(k & 3) * 2u + (u32)(k >> 2) * 1024u;
                        u32 bo = (u32)(k & 3) * 2u + (u32)(k >> 2) * bstr;
                        tc_mma(d_hid, ad + ao, bd + bo, idesc, (u32)(k > 0));
                    }
                    asm volatile(
                        "tcgen05.commit.cta_group::1.mbarrier::arrive::one.shared::cluster.b64 [%0];"
                        :: "r"(mbar) : "memory");
                }
            }
        }

        #pragma unroll
        for (int s = 0; s < 2; s++) {
            const u32 mbar = sb + 8u + 8u * (u32)s;
            mbar_wait_b(mbar, ph[s]);
            ph[s] ^= 1;
            asm volatile("tcgen05.fence::after_thread_sync;" ::: "memory");
            if (half == 0) {
                u32 r16[16];
                LDTM_X16(r16, tmem + (u32)s * 128u);
                asm volatile("tcgen05.wait::ld.sync.aligned;" ::: "memory");
                if (probe) {
                    asm volatile("st.shared.v4.b32 [%0], {%1,%2,%3,%4};"
                        :: "r"(sb + ACT[s] + (u32)myrow * 128u),
                           "r"(r16[0]), "r"(r16[1]), "r"(r16[2]), "r"(r16[3])
                        : "memory");
                } else {
                    float* op = out + ((u64)(t0 + s) * 128u + (u64)myrow) * 16u;
                    #pragma unroll
                    for (int q = 0; q < 4; q++) {
                        float a0 = __uint_as_float(r16[4 * q])     + bz[4 * q];
                        float a1 = __uint_as_float(r16[4 * q + 1]) + bz[4 * q + 1];
                        float a2 = __uint_as_float(r16[4 * q + 2]) + bz[4 * q + 2];
                        float a3 = __uint_as_float(r16[4 * q + 3]) + bz[4 * q + 3];
                        asm volatile("st.global.v4.f32 [%0], {%1,%2,%3,%4};"
                            :: "l"(op + 4 * q), "f"(a0), "f"(a1), "f"(a2), "f"(a3)
                            : "memory");
                    }
                }
            }
        }
        __syncthreads();
    }
    __syncthreads();
    if (wid == 0)
        asm volatile("tcgen05.dealloc.cta_group::1.sync.aligned.b32 %0, %1;"
                     :: "r"(tmem), "r"(512u));
}

extern "C" __global__ void __launch_bounds__(128, 1) tc_probe_basic()
{
    extern __shared__ char smem[];
    u32 sb;
    asm("{.reg .u64 t; cvta.to.shared.u64 t, %1; cvt.u32.u64 %0, t;}"
        : "=r"(sb) : "l"(smem));
    int tid = threadIdx.x, wid = tid >> 5;
    if (wid == 0) {
        asm volatile("tcgen05.alloc.cta_group::1.sync.aligned.shared::cta.b32 [%0], %1;"
                     :: "r"(sb), "r"(512u) : "memory");
        asm volatile("tcgen05.relinquish_alloc_permit.cta_group::1.sync.aligned;");
    }
    if (tid == 0) MBAR_INIT(sb + 8, 1);
    for (int i = tid; i < 8192; i += 128) {
        st_h(sb + SACT0 + (u32)i * 2u, 0.1f);
        st_h(sb + SW1 + (u32)i * 2u, 0.2f);
    }
    asm volatile("fence.proxy.async.shared::cta;" ::: "memory");
    __syncthreads();
    u32 tmem;
    asm volatile("ld.shared.b32 %0, [%1];" : "=r"(tmem) : "r"(sb));
    if (wid == 0 && elect1()) {
        tc_mma(tmem, mdesc(sb + SACT0), mdesc(sb + SW1), IDESC_N128, 0u);
        asm volatile(
            "tcgen05.commit.cta_group::1.mbarrier::arrive::one.shared::cluster.b64 [%0];"
            :: "r"(sb + 8) : "memory");
    }
    mbar_wait_b(sb + 8, 0);
    asm volatile("tcgen05.fence::after_thread_sync;" ::: "memory");
    u32 r[32];
    LDTM_X32(r, tmem);
    asm volatile("tcgen05.wait::ld.sync.aligned;" ::: "memory");
    asm volatile("st.shared.b32 [%0], %1;"
                 :: "r"(sb + SACT0 + (u32)tid * 4u), "r"(r[0]) : "memory");
    __syncthreads();
    if (wid == 0)
        asm volatile("tcgen05.dealloc.cta_group::1.sync.aligned.b32 %0, %1;"
                     :: "r"(tmem), "r"(512u));
}
)___";

#define TC_SMEM 218112
#define TC_NTILES 4096

static CUfunction g_tc_fn = nullptr;
static int g_tc_ok = 0;
static int g_sm = 148;

typedef CUresult (*PFN_cuInit)(unsigned int);
typedef CUresult (*PFN_cuDeviceGet)(CUdevice*, int);
typedef CUresult (*PFN_cuDeviceGetAttribute)(int*, CUdevice_attribute, CUdevice);
typedef CUresult (*PFN_cuDevicePrimaryCtxRetain)(CUcontext*, CUdevice);
typedef CUresult (*PFN_cuDevicePrimaryCtxReset)(CUdevice);
typedef CUresult (*PFN_cuCtxSetCurrent)(CUcontext);
typedef CUresult (*PFN_cuCtxSynchronize)(void);
typedef CUresult (*PFN_cuModuleLoadData)(CUmodule*, const void*);
typedef CUresult (*PFN_cuModuleGetFunction)(CUfunction*, CUmodule, const char*);
typedef CUresult (*PFN_cuFuncSetAttribute)(CUfunction, CUfunction_attribute, int);
typedef CUresult (*PFN_cuLaunchKernel)(CUfunction, unsigned, unsigned, unsigned,
                                       unsigned, unsigned, unsigned, unsigned,
                                       CUstream, void**, void**);
typedef nvrtcResult (*PFN_nvrtcCreateProgram)(nvrtcProgram*, const char*, const char*,
                                              int, const char* const*, const char* const*);
typedef nvrtcResult (*PFN_nvrtcCompileProgram)(nvrtcProgram, int, const char* const*);
typedef nvrtcResult (*PFN_nvrtcGetCUBINSize)(nvrtcProgram, size_t*);
typedef nvrtcResult (*PFN_nvrtcGetCUBIN)(nvrtcProgram, char*);
typedef nvrtcResult (*PFN_nvrtcGetProgramLogSize)(nvrtcProgram, size_t*);
typedef nvrtcResult (*PFN_nvrtcGetProgramLog)(nvrtcProgram, char*);

static PFN_cuLaunchKernel p_cuLaunchKernel = nullptr;

__attribute__((constructor))
static void _tc_ctor() {
    void* hc = dlopen("libcuda.so.1", RTLD_NOW | RTLD_GLOBAL);
    if (!hc) hc = dlopen("libcuda.so", RTLD_NOW | RTLD_GLOBAL);
    if (!hc) { fprintf(stderr, "[tc] no libcuda\n"); return; }
    void* hn = nullptr;
    const char* names[] = {"libnvrtc.so.13", "libnvrtc.so.12", "libnvrtc.so",
                           "/usr/local/cuda/lib64/libnvrtc.so", nullptr};
    for (int i = 0; names[i] && !hn; i++) hn = dlopen(names[i], RTLD_NOW | RTLD_GLOBAL);
    if (!hn) { fprintf(stderr, "[tc] no libnvrtc\n"); return; }

    PFN_cuInit f_cuInit = (PFN_cuInit)dlsym(hc, "cuInit");
    PFN_cuDeviceGet f_cuDeviceGet = (PFN_cuDeviceGet)dlsym(hc, "cuDeviceGet");
    PFN_cuDeviceGetAttribute f_cuDevAttr =
        (PFN_cuDeviceGetAttribute)dlsym(hc, "cuDeviceGetAttribute");
    PFN_cuDevicePrimaryCtxRetain f_cuRetain =
        (PFN_cuDevicePrimaryCtxRetain)dlsym(hc, "cuDevicePrimaryCtxRetain");
    PFN_cuDevicePrimaryCtxReset f_cuReset =
        (PFN_cuDevicePrimaryCtxReset)dlsym(hc, "cuDevicePrimaryCtxReset");
    PFN_cuCtxSetCurrent f_cuSetCur = (PFN_cuCtxSetCurrent)dlsym(hc, "cuCtxSetCurrent");
    PFN_cuCtxSynchronize f_cuSync = (PFN_cuCtxSynchronize)dlsym(hc, "cuCtxSynchronize");
    PFN_cuModuleLoadData f_cuModLoad = (PFN_cuModuleLoadData)dlsym(hc, "cuModuleLoadData");
    PFN_cuModuleGetFunction f_cuModFn =
        (PFN_cuModuleGetFunction)dlsym(hc, "cuModuleGetFunction");
    PFN_cuFuncSetAttribute f_cuFnAttr =
        (PFN_cuFuncSetAttribute)dlsym(hc, "cuFuncSetAttribute");
    p_cuLaunchKernel = (PFN_cuLaunchKernel)dlsym(hc, "cuLaunchKernel");
    PFN_nvrtcCreateProgram f_nCreate = (PFN_nvrtcCreateProgram)dlsym(hn, "nvrtcCreateProgram");
    PFN_nvrtcCompileProgram f_nCompile =
        (PFN_nvrtcCompileProgram)dlsym(hn, "nvrtcCompileProgram");
    PFN_nvrtcGetCUBINSize f_nCubSz = (PFN_nvrtcGetCUBINSize)dlsym(hn, "nvrtcGetCUBINSize");
    PFN_nvrtcGetCUBIN f_nCub = (PFN_nvrtcGetCUBIN)dlsym(hn, "nvrtcGetCUBIN");
    PFN_nvrtcGetProgramLogSize f_nLogSz =
        (PFN_nvrtcGetProgramLogSize)dlsym(hn, "nvrtcGetProgramLogSize");
    PFN_nvrtcGetProgramLog f_nLog = (PFN_nvrtcGetProgramLog)dlsym(hn, "nvrtcGetProgramLog");
    if (!f_cuInit || !f_cuDeviceGet || !f_cuRetain || !f_cuReset || !f_cuSetCur ||
        !f_cuSync || !f_cuModLoad || !f_cuModFn || !f_cuFnAttr || !p_cuLaunchKernel ||
        !f_nCreate || !f_nCompile || !f_nCubSz || !f_nCub) {
        fprintf(stderr, "[tc] dlsym missing\n"); return;
    }

    if (f_cuInit(0) != CUDA_SUCCESS) { fprintf(stderr, "[tc] cuInit fail\n"); return; }
    CUdevice dev; CUcontext ctx;
    if (f_cuDeviceGet(&dev, 0) != CUDA_SUCCESS) return;
    if (f_cuDevAttr) f_cuDevAttr(&g_sm, CU_DEVICE_ATTRIBUTE_MULTIPROCESSOR_COUNT, dev);
    if (f_cuRetain(&ctx, dev) != CUDA_SUCCESS) { fprintf(stderr, "[tc] ctx fail\n"); return; }
    f_cuSetCur(ctx);

    nvrtcProgram prog;
    if (f_nCreate(&prog, TC_SRC, "tc.cu", 0, nullptr, nullptr) != NVRTC_SUCCESS) return;
    const char* opts[] = {"--gpu-architecture=sm_103a"};
    nvrtcResult cr = f_nCompile(prog, 1, opts);
    if (cr != NVRTC_SUCCESS) {
        size_t lsz = 0;
        if (f_nLogSz && f_nLog && f_nLogSz(prog, &lsz) == NVRTC_SUCCESS && lsz > 1) {
            char* lg = (char*)malloc(lsz);
            f_nLog(prog, lg);
            fprintf(stderr, "[tc] nvrtc log: %.2000s\n", lg);
            free(lg);
        }
        return;
    }
    size_t isz = 0;
    if (f_nCubSz(prog, &isz) != NVRTC_SUCCESS || isz == 0) return;
    char* image = (char*)malloc(isz);
    if (f_nCub(prog, image) != NVRTC_SUCCESS) { free(image); return; }

    CUmodule mod; CUfunction fn = nullptr;
    if (f_cuModLoad(&mod, image) != CUDA_SUCCESS) {
        fprintf(stderr, "[tc] modload fail\n"); free(image); return;
    }
    if (f_cuModFn(&fn, mod, "mlp_tc") != CUDA_SUCCESS) { free(image); return; }
    f_cuFnAttr(fn, CU_FUNC_ATTRIBUTE_MAX_DYNAMIC_SHARED_SIZE_BYTES, TC_SMEM);

    void* zp = nullptr; int g2 = 2, nt = 8, pb = 1;
    void* prm[12] = {&zp, &zp, &zp, &zp, &zp, &zp, &zp, &zp, &zp, &g2, &nt, &pb};
    CUresult lr = p_cuLaunchKernel(fn, 2, 1, 1, 256, 1, 1, TC_SMEM,
                                   (CUstream)0, prm, nullptr);
    CUresult sr = (lr == CUDA_SUCCESS) ? f_cuSync() : lr;
    if (sr == CUDA_SUCCESS) {
        g_tc_fn = fn;
        g_tc_ok = 1;
        fprintf(stderr, "[tc] probe_full OK — pipelined tcgen05 live (sm=%d)\n", g_sm);
        free(image);
        return;
    }
    fprintf(stderr, "[tc] probe_full FAIL %d — resetting ctx, basic probe\n", (int)sr);
    f_cuReset(dev);

    if (f_cuRetain(&ctx, dev) == CUDA_SUCCESS) {
        f_cuSetCur(ctx);
        CUmodule mod2; CUfunction fb = nullptr;
        if (f_cuModLoad(&mod2, image) == CUDA_SUCCESS &&
            f_cuModFn(&fb, mod2, "tc_probe_basic") == CUDA_SUCCESS) {
            f_cuFnAttr(fb, CU_FUNC_ATTRIBUTE_MAX_DYNAMIC_SHARED_SIZE_BYTES, TC_SMEM);
            CUresult l2 = p_cuLaunchKernel(fb, 1, 1, 1, 128, 1, 1, TC_SMEM,
                                           (CUstream)0, nullptr, nullptr);
            CUresult s2 = (l2 == CUDA_SUCCESS) ? f_cuSync() : l2;
            fprintf(stderr, "[tc] probe_basic result: %d\n", (int)s2);
        } else {
            fprintf(stderr, "[tc] probe_basic load fail\n");
        }
        f_cuReset(dev);
    }
    free(image);
    g_tc_ok = 0;
}

// ============================================================================
// Fallback: proven R7 HMMA kernel (182.8 us).
// ============================================================================
#define NSAMP   524288
#define MTILE   256
#define NTILES  (NSAMP / MTILE)
#define NTHREADS 512
#define DIMO    16
#define SW0   0
#define SW1   16384
#define SW2   49152
#define SW3   81920
#define SW4   114688
#define SW5   147456
#define SX    153600
#define XSTR  144
#define SMEM_TOTAL (SX + 256 * XSTR)

__device__ __forceinline__ uint32_t smem_u32(const void* p) {
    uint32_t a;
    asm("{ .reg .u64 t; cvta.to.shared.u64 t, %1; cvt.u32.u64 %0, t; }"
        : "=r"(a) : "l"(p));
    return a;
}
__device__ __forceinline__ void ldsm_x4(uint32_t* r, uint32_t addr) {
    asm volatile("ldmatrix.sync.aligned.m8n8.x4.shared.b16 {%0,%1,%2,%3}, [%4];"
                 : "=r"(r[0]), "=r"(r[1]), "=r"(r[2]), "=r"(r[3]) : "r"(addr));
}
__device__ __forceinline__ void ldsm_x4t(uint32_t* r, uint32_t addr) {
    asm volatile("ldmatrix.sync.aligned.m8n8.x4.trans.shared.b16 {%0,%1,%2,%3}, [%4];"
                 : "=r"(r[0]), "=r"(r[1]), "=r"(r[2]), "=r"(r[3]) : "r"(addr));
}
__device__ __forceinline__ void mma16816(float* c, const uint32_t* a,
                                         uint32_t b0, uint32_t b1) {
    asm volatile(
        "mma.sync.aligned.m16n8k16.row.col.f32.f16.f16.f32 "
        "{%0,%1,%2,%3}, {%4,%5,%6,%7}, {%8,%9}, {%0,%1,%2,%3};"
        : "+f"(c[0]), "+f"(c[1]), "+f"(c[2]), "+f"(c[3])
        : "r"(a[0]), "r"(a[1]), "r"(a[2]), "r"(a[3]), "r"(b0), "r"(b1));
}
__device__ __forceinline__ void mma16816_z(float* c, const uint32_t* a,
                                           uint32_t b0, uint32_t b1) {
    asm volatile(
        "mma.sync.aligned.m16n8k16.row.col.f32.f16.f16.f32 "
        "{%0,%1,%2,%3}, {%4,%5,%6,%7}, {%8,%9}, {%10,%10,%10,%10};"
        : "=f"(c[0]), "=f"(c[1]), "=f"(c[2]), "=f"(c[3])
        : "r"(a[0]), "r"(a[1]), "r"(a[2]), "r"(a[3]), "r"(b0), "r"(b1),
          "f"(0.0f));
}
__device__ __forceinline__ uint32_t relu_pack(float a, float b) {
    __half2 h = __floats2half2_rn(a, b);
    h = __hmax2(h, __floats2half2_rn(0.0f, 0.0f));
    return *(uint32_t*)&h;
}

__global__ void __launch_bounds__(NTHREADS, 1)
mlp_chain2_kernel(const float* __restrict__ x,
                  const float* __restrict__ gW0, const float* __restrict__ gW1,
                  const float* __restrict__ gW2, const float* __restrict__ gW3,
                  const float* __restrict__ gW4, const float* __restrict__ gW5,
                  const float* __restrict__ bias,
                  float* __restrict__ out) {
    extern __shared__ char smem[];
    const uint32_t sb = smem_u32(smem);
    const int tid  = threadIdx.x;
    const int wid  = tid >> 5;
    const int lane = tid & 31;

    {
        const float* gws[5] = {gW0, gW1, gW2, gW3, gW4};
        const uint32_t so[5] = {SW0, SW1, SW2, SW3, SW4};
        const int rows[5] = {64, 128, 128, 128, 128};
        #pragma unroll
        for (int w = 0; w < 5; w++) {
            for (int i = tid; i < rows[w] * 32; i += NTHREADS) {
                int k = i >> 5, n4 = i & 31;
                float4 v = ((const float4*)gws[w])[i];
                __half2 h0 = __floats2half2_rn(v.x, v.y), h1 = __floats2half2_rn(v.z, v.w);
                uint2 p = make_uint2(*(uint32_t*)&h0, *(uint32_t*)&h1);
                int c = n4 >> 1;
                int swc = (c & 8) | ((c ^ (k & 7)) & 7);
                *(uint2*)(smem + so[w] + k * 256 + swc * 16 + (n4 & 1) * 8) = p;
            }
        }
    }
    for (int i = tid; i < 128 * 4; i += NTHREADS) {
        int k = i >> 2, n4 = i & 3;
        float4 v = ((const float4*)gW5)[i];
        __half2 h0 = __floats2half2_rn(v.x, v.y), h1 = __floats2half2_rn(v.z, v.w);
        uint2 p = make_uint2(*(uint32_t*)&h0, *(uint32_t*)&h1);
        *(uint2*)(smem + SW5 + k * 48 + n4 * 8) = p;
    }

    const int col0 = (lane & 3) * 2;
    const int row0 = lane >> 2;
    float bz0 = __ldg(bias + col0);
    float bz1 = __ldg(bias + col0 + 1);
    float bz2 = __ldg(bias + 8 + col0);
    float bz3 = __ldg(bias + 9 + col0);

    __syncthreads();

    const int lrow = lane & 15;
    const int lhi  = lane >> 4;
    const int lr7  = lrow & 7;
    const uint32_t aA = sb + SX + (16 * wid + lrow) * XSTR + lhi * 16;
    const uint32_t w5a = sb + SW5 + (uint32_t)lrow * 48 + lhi * 16;
    const uint32_t xsts_row = SX + 16 * wid * XSTR;

    uint32_t joff[8];
    #pragma unroll
    for (int j = 0; j < 8; j++) {
        int c = 2 * j + lhi;
        int swc = (c & 8) | ((c ^ lr7) & 7);
        joff[j] = (uint32_t)lrow * 256 + swc * 16;
    }

    const int G = gridDim.x;
    {
        const float4* xg = (const float4*)(x + (size_t)blockIdx.x * MTILE * 64)
                         + wid * 256;
        #pragma unroll
        for (int it = 0; it < 8; it++) {
            int idx = lane + it * 32;
            int r = idx >> 4, c4 = idx & 15;
            float4 v = xg[idx];
            __half2 h0 = __floats2half2_rn(v.x, v.y), h1 = __floats2half2_rn(v.z, v.w);
            uint2 p = make_uint2(*(uint32_t*)&h0, *(uint32_t*)&h1);
            *(uint2*)(smem + xsts_row + r * XSTR + c4 * 8) = p;
        }
    }

    for (int t = blockIdx.x; t < NTILES; t += G) {
        __syncwarp();
        uint32_t A[8][4];
        #pragma unroll
        for (int kb = 0; kb < 4; kb++) ldsm_x4(A[kb], aA + kb * 32);

        float C[16][4];
        #pragma unroll
        for (int j = 0; j < 8; j++) {
            uint32_t B[4];
            ldsm_x4t(B, sb + SW0 + joff[j]);
            mma16816_z(C[2 * j],     A[0], B[0], B[1]);
            mma16816_z(C[2 * j + 1], A[0], B[2], B[3]);
        }
        #pragma unroll
        for (int kb = 1; kb < 4; kb++)
            #pragma unroll
            for (int j = 0; j < 8; j++) {
                uint32_t B[4];
                ldsm_x4t(B, sb + SW0 + kb * 4096 + joff[j]);
                mma16816(C[2 * j],     A[kb], B[0], B[1]);
                mma16816(C[2 * j + 1], A[kb], B[2], B[3]);
            }

        const int tn = t + G;
        const bool pf = tn < NTILES;
        const float4* xgn = (const float4*)(x + (size_t)tn * MTILE * 64) + wid * 256;
        float4 vb[4];
        if (pf) {
            #pragma unroll
            for (int it = 0; it < 4; it++) vb[it] = xgn[lane + it * 32];
        }

        const uint32_t WS[4] = {SW1, SW2, SW3, SW4};
        #pragma unroll
        for (int l = 0; l < 4; l++) {
            #pragma unroll
            for (int j = 0; j < 8; j++) {
                A[j][0] = relu_pack(C[2 * j][0],     C[2 * j][1]);
                A[j][1] = relu_pack(C[2 * j][2],     C[2 * j][3]);
                A[j][2] = relu_pack(C[2 * j + 1][0], C[2 * j + 1][1]);
                A[j][3] = relu_pack(C[2 * j + 1][2], C[2 * j + 1][3]);
            }
            const uint32_t wb = sb + WS[l];
            #pragma unroll
            for (int j = 0; j < 8; j++) {
                uint32_t B[4];
                ldsm_x4t(B, wb + joff[j]);
                mma16816_z(C[2 * j],     A[0], B[0], B[1]);
                mma16816_z(C[2 * j + 1], A[0], B[2], B[3]);
            }
            #pragma unroll
            for (int kb = 1; kb < 8; kb++)
                #pragma unroll
                for (int j = 0; j < 8; j++) {
                    uint32_t B[4];
                    ldsm_x4t(B, wb + kb * 4096 + joff[j]);
                    mma16816(C[2 * j],     A[kb], B[0], B[1]);
                    mma16816(C[2 * j + 1], A[kb], B[2], B[3]);
                }
            if (l == 0 && pf) {
                #pragma unroll
                for (int it = 0; it < 4; it++) {
                    int idx = lane + it * 32;
                    int r = idx >> 4, c4 = idx & 15;
                    __half2 h0 = __floats2half2_rn(vb[it].x, vb[it].y);
                    __half2 h1 = __floats2half2_rn(vb[it].z, vb[it].w);
                    uint2 p = make_uint2(*(uint32_t*)&h0, *(uint32_t*)&h1);
                    *(uint2*)(smem + xsts_row + r * XSTR + c4 * 8) = p;
                }
                #pragma unroll
                for (int it = 0; it < 4; it++) vb[it] = xgn[lane + (it + 4) * 32];
            }
            if (l == 1 && pf) {
                #pragma unroll
                for (int it = 0; it < 4; it++) {
                    int idx = lane + (it + 4) * 32;
                    int r = idx >> 4, c4 = idx & 15;
                    __half2 h0 = __floats2half2_rn(vb[it].x, vb[it].y);
                    __half2 h1 = __floats2half2_rn(vb[it].z, vb[it].w);
                    uint2 p = make_uint2(*(uint32_t*)&h0, *(uint32_t*)&h1);
                    *(uint2*)(smem + xsts_row + r * XSTR + c4 * 8) = p;
                }
            }
        }

        #pragma unroll
        for (int j = 0; j < 8; j++) {
            A[j][0] = relu_pack(C[2 * j][0],     C[2 * j][1]);
            A[j][1] = relu_pack(C[2 * j][2],     C[2 * j][3]);
            A[j][2] = relu_pack(C[2 * j + 1][0], C[2 * j + 1][1]);
            A[j][3] = relu_pack(C[2 * j + 1][2], C[2 * j + 1][3]);
        }
        float C5[2][4];
        {
            uint32_t B[4];
            ldsm_x4t(B, w5a);
            mma16816_z(C5[0], A[0], B[0], B[1]);
            mma16816_z(C5[1], A[0], B[2], B[3]);
        }
        #pragma unroll
        for (int kb = 1; kb < 8; kb++) {
            uint32_t B[4];
            ldsm_x4t(B, w5a + kb * 768);
            mma16816(C5[0], A[kb], B[0], B[1]);
            mma16816(C5[1], A[kb], B[2], B[3]);
        }

        const size_t g0 = ((size_t)t * MTILE + 16 * wid + row0) * DIMO;
        const size_t g1 = g0 + 8 * DIMO;
        float2 v;
        v.x = C5[0][0] + bz0; v.y = C5[0][1] + bz1;
        *(float2*)(out + g0 + col0) = v;
        v.x = C5[1][0] + bz2; v.y = C5[1][1] + bz3;
        *(float2*)(out + g0 + 8 + col0) = v;
        v.x = C5[0][2] + bz0; v.y = C5[0][3] + bz1;
        *(float2*)(out + g1 + col0) = v;
        v.x = C5[1][2] + bz2; v.y = C5[1][3] + bz3;
        *(float2*)(out + g1 + 8 + col0) = v;
    }
}

static CUstream _pick_stream() {
    cudaStreamCaptureStatus s = cudaStreamCaptureStatusNone;
    if (cudaStreamIsCapturing((cudaStream_t)0x2, &s) == cudaSuccess &&
        s == cudaStreamCaptureStatusActive)
        return (CUstream)0x2;
    s = cudaStreamCaptureStatusNone;
    if (cudaStreamIsCapturing((cudaStream_t)0x1, &s) == cudaSuccess &&
        s == cudaStreamCaptureStatusActive)
        return (CUstream)0x1;
#ifdef CUDA_API_PER_THREAD_DEFAULT_STREAM
    return (CUstream)0x2;
#else
    return (CUstream)0x1;
#endif
}

extern "C" void kernel_launch(void* const* d_in, const int* in_sizes, int n_in,
                              void* d_out, int out_size) {
    const float* x    = (const float*)d_in[0];
    const float* W0   = (const float*)d_in[1];
    const float* W1   = (const float*)d_in[2];
    const float* W2   = (const float*)d_in[3];
    const float* W3   = (const float*)d_in[4];
    const float* W4   = (const float*)d_in[5];
    const float* W5   = (const float*)d_in[6];
    const float* bias = (const float*)d_in[7];
    float* out = (float*)d_out;

    if (g_tc_ok && g_tc_fn && p_cuLaunchKernel) {
        int grid = g_sm, ntiles = TC_NTILES, probe = 0;
        void* params[12] = {(void*)&x, (void*)&W0, (void*)&W1, (void*)&W2,
                            (void*)&W3, (void*)&W4, (void*)&W5, (void*)&bias,
                            (void*)&out, (void*)&grid, (void*)&ntiles,
                            (void*)&probe};
        CUresult r = p_cuLaunchKernel(g_tc_fn, (unsigned)grid, 1, 1, 256, 1, 1,
                                      TC_SMEM, _pick_stream(), params, nullptr);
        if (r == CUDA_SUCCESS) return;
        fprintf(stderr, "[tc] real launch fail %d — falling back\n", (int)r);
        g_tc_ok = 0;
    }

    cudaFuncSetAttribute(mlp_chain2_kernel,
                         cudaFuncAttributeMaxDynamicSharedMemorySize, SMEM_TOTAL);
    int sm = 148;
    cudaDeviceGetAttribute(&sm, cudaDevAttrMultiProcessorCount, 0);
    int grid = sm < NTILES ? sm : NTILES;
    mlp_chain2_kernel<<<grid, NTHREADS, SMEM_TOTAL>>>(x, W0, W1, W2, W3, W4, W5,
                                                      bias, out);
}

// round 13
// speedup vs baseline: 1.2186x; 1.2186x over previous
#include <cuda_runtime.h>
#include <cuda_fp16.h>
#include <cuda.h>
#include <nvrtc.h>
#include <dlfcn.h>
#include <cstdio>
#include <cstdlib>
#include <cstring>
#include <cstdint>

// ============================================================================
// Embedded tcgen05 kernel (NVRTC, --gpu-architecture=sm_103a).
// 512 threads = TWO independent 8-warp teams (R10 structure), each team owns
// one M=128 tile stream. Epilogue split: 2 warps per TMEM subpartition, each
// handling one 64-column half (R11-validated addressing).
// probe=1 keeps identical instruction structure with global accesses guarded.
// ============================================================================
static const char* TC_SRC = R"___(
typedef unsigned int u32;
typedef unsigned long long u64;

#define SW0   1024u
#define SW1   17408u
#define SW2   50176u
#define SW3   82944u
#define SW4   115712u
#define SW5   148480u
#define SACT0 152576u
#define SACT1 185344u
#define IDESC_N128 ((1u<<4) | (16u<<17) | (8u<<24))
#define IDESC_N16  ((1u<<4) | ( 2u<<17) | (8u<<24))

__device__ __forceinline__ u32 swz(u32 o) { return o ^ ((o >> 3) & 0x70u); }

__device__ __forceinline__ u64 mdesc(u32 addr) {
    return ((u64)2 << 61) | ((u64)1 << 46) | ((u64)64 << 32) | ((u64)1 << 16)
         | ((u64)(addr >> 4) & 0x3FFFu);
}
__device__ __forceinline__ void st_h(u32 a, float v) {
    asm volatile("{.reg .b16 h; cvt.rn.f16.f32 h, %1; st.shared.b16 [%0], h;}"
                 :: "r"(a), "f"(v) : "memory");
}
__device__ __forceinline__ u32 rpack(float a, float b) {
    u32 r;
    asm("cvt.rn.f16x2.f32 %0, %1, %2;" : "=r"(r) : "f"(b), "f"(a));
    asm("max.f16x2 %0, %0, %1;" : "+r"(r) : "r"(0u));
    return r;
}
__device__ __forceinline__ void tc_mma(u32 d, u64 a, u64 b, u32 id, u32 en) {
    asm volatile("{.reg .pred p; setp.ne.u32 p, %4, 0;\n\t"
        "tcgen05.mma.cta_group::1.kind::f16 [%0], %1, %2, %3, {%5,%5,%5,%5}, p;}"
        :: "r"(d), "l"(a), "l"(b), "r"(id), "r"(en), "r"(0u) : "memory");
}
__device__ __forceinline__ bool elect1() {
    u32 p;
    asm volatile("{.reg .pred p; elect.sync _|p, 0xFFFFFFFF; selp.b32 %0,1,0,p;}"
                 : "=r"(p));
    return p != 0;
}
#define MBAR_INIT(mb, c) \
    asm volatile("mbarrier.init.shared.b64 [%0], %1;" \
        :: "r"((u32)(mb)), "r"((u32)(c)) : "memory")
__device__ __forceinline__ void mbar_wait_b(u32 mb, u32 par) {
    for (int i = 0; i < 4096; i++) {
        u32 d;
        asm volatile("{.reg .pred p;\n\t"
            "mbarrier.try_wait.parity.acquire.cta.shared::cta.b64 p, [%1], %2, 0x989680;\n\t"
            "selp.b32 %0,1,0,p;}" : "=r"(d) : "r"(mb), "r"(par) : "memory");
        if (d) return;
    }
}
#define LDTM_X32(r, a) \
    asm volatile("tcgen05.ld.sync.aligned.32x32b.x32.b32 " \
        "{%0,%1,%2,%3,%4,%5,%6,%7,%8,%9,%10,%11,%12,%13,%14,%15," \
        "%16,%17,%18,%19,%20,%21,%22,%23,%24,%25,%26,%27,%28,%29,%30,%31}, [%32];" \
        : "=r"((r)[0]),"=r"((r)[1]),"=r"((r)[2]),"=r"((r)[3]), \
          "=r"((r)[4]),"=r"((r)[5]),"=r"((r)[6]),"=r"((r)[7]), \
          "=r"((r)[8]),"=r"((r)[9]),"=r"((r)[10]),"=r"((r)[11]), \
          "=r"((r)[12]),"=r"((r)[13]),"=r"((r)[14]),"=r"((r)[15]), \
          "=r"((r)[16]),"=r"((r)[17]),"=r"((r)[18]),"=r"((r)[19]), \
          "=r"((r)[20]),"=r"((r)[21]),"=r"((r)[22]),"=r"((r)[23]), \
          "=r"((r)[24]),"=r"((r)[25]),"=r"((r)[26]),"=r"((r)[27]), \
          "=r"((r)[28]),"=r"((r)[29]),"=r"((r)[30]),"=r"((r)[31]) \
        : "r"(a))
#define LDTM_X16(r, a) \
    asm volatile("tcgen05.ld.sync.aligned.32x32b.x16.b32 " \
        "{%0,%1,%2,%3,%4,%5,%6,%7,%8,%9,%10,%11,%12,%13,%14,%15}, [%16];" \
        : "=r"((r)[0]),"=r"((r)[1]),"=r"((r)[2]),"=r"((r)[3]), \
          "=r"((r)[4]),"=r"((r)[5]),"=r"((r)[6]),"=r"((r)[7]), \
          "=r"((r)[8]),"=r"((r)[9]),"=r"((r)[10]),"=r"((r)[11]), \
          "=r"((r)[12]),"=r"((r)[13]),"=r"((r)[14]),"=r"((r)[15]) \
        : "r"(a))

extern "C" __global__ void __launch_bounds__(512, 1)
mlp_tc(const float* x, const float* gW0, const float* gW1, const float* gW2,
       const float* gW3, const float* gW4, const float* gW5,
       const float* bias, float* out, int grid, int ntiles, int probe)
{
    extern __shared__ char smem[];
    u32 sb;
    asm("{.reg .u64 t; cvta.to.shared.u64 t, %1; cvt.u32.u64 %0, t;}"
        : "=r"(sb) : "l"(smem));
    const int tid  = threadIdx.x;
    const int lane = tid & 31;
    const int team = tid >> 8;            // 0 or 1
    const int ttid = tid & 255;           // thread within team
    const int twid = ttid >> 5;           // warp within team: 0..7
    const int sub  = twid & 3;            // TMEM subpartition (= wid%4 globally)
    const int half = (twid >> 2) & 1;     // 64-col half owned by this warp
    const int myrow = sub * 32 + lane;

    if (tid < 32) {
        asm volatile("tcgen05.alloc.cta_group::1.sync.aligned.shared::cta.b32 [%0], %1;"
                     :: "r"(sb), "r"(512u) : "memory");
        asm volatile("tcgen05.relinquish_alloc_permit.cta_group::1.sync.aligned;");
    }
    if (tid == 0) { MBAR_INIT(sb + 8, 1); MBAR_INIT(sb + 16, 1); }

    // ---- weights -> fp16 SMEM, [N rows x K cols] SW128 blocked-atom ----
    {
        const float* gws[4] = {gW1, gW2, gW3, gW4};
        const u32 so[4] = {SW1, SW2, SW3, SW4};
        for (int w = 0; w < 4; w++)
            for (int i = tid; i < 128 * 128; i += 512) {
                int k = i >> 7, n = i & 127;
                u32 off = (u32)(k >> 6) * 16384u + (u32)n * 128u + (u32)(k & 63) * 2u;
                float v = probe ? 0.03f : gws[w][i];
                st_h(sb + so[w] + swz(off), v);
            }
    }
    for (int i = tid; i < 64 * 128; i += 512) {
        int k = i >> 7, n = i & 127;
        u32 off = (u32)n * 128u + (u32)k * 2u;
        float v = probe ? 0.02f : gW0[i];
        st_h(sb + SW0 + swz(off), v);
    }
    for (int i = tid; i < 128 * 16; i += 512) {
        int k = i >> 4, n = i & 15;
        u32 off = (u32)(k >> 6) * 2048u + (u32)n * 128u + (u32)(k & 63) * 2u;
        float v = probe ? 0.01f : gW5[i];
        st_h(sb + SW5 + swz(off), v);
    }
    float bz[16];
    for (int i = 0; i < 16; i++) bz[i] = probe ? 0.0f : bias[i];

    asm volatile("fence.proxy.async.shared::cta;" ::: "memory");
    __syncthreads();
    u32 tmem;
    asm volatile("ld.shared.b32 %0, [%1];" : "=r"(tmem) : "r"(sb));

    const u32 actb  = (team == 0) ? SACT0 : SACT1;
    const u32 mbar  = sb + 8u + 8u * (u32)team;
    const u32 d_hid = tmem + (u32)team * 128u;
    const u32 d_out = tmem + 256u + (u32)team * 16u;
    const u64 adesc = mdesc(sb + actb);
    const int barid = team + 1;
    const bool leader = (twid == 0);
    const u32 WB[6] = {SW0, SW1, SW2, SW3, SW4, SW5};

    u32 ph = 0;

    for (int t = blockIdx.x * 2 + team; t < ntiles; t += 2 * grid) {
        // ---- x tile [128 x 64] fp32 -> fp16 SW128 (team-wide, 256 threads) ----
        const float* xg = x + (u64)t * 128u * 64u;
        #pragma unroll
        for (int it = 0; it < 8; it++) {
            int idx = ttid + it * 256;
            int r = idx >> 4, c4 = idx & 15;
            float vx, vy, vz, vw;
            if (probe) {
                vx = (float)(idx & 7) * 0.05f; vy = 0.2f; vz = -0.1f; vw = 0.15f;
            } else {
                asm("ld.global.nc.v4.f32 {%0,%1,%2,%3}, [%4];"
                    : "=f"(vx), "=f"(vy), "=f"(vz), "=f"(vw)
                    : "l"(xg + 4 * idx));
            }
            u32 p0, p1;
            asm("cvt.rn.f16x2.f32 %0, %1, %2;" : "=r"(p0) : "f"(vy), "f"(vx));
            asm("cvt.rn.f16x2.f32 %0, %1, %2;" : "=r"(p1) : "f"(vw), "f"(vz));
            u32 a = sb + actb + swz((u32)r * 128u + (u32)c4 * 8u);
            asm volatile("st.shared.v2.b32 [%0], {%1,%2};"
                         :: "r"(a), "r"(p0), "r"(p1) : "memory");
        }
        asm volatile("fence.proxy.async.shared::cta;" ::: "memory");
        asm volatile("bar.sync %0, 256;" :: "r"(barid) : "memory");

        // ---- layer 0 MMA: K=64 SS ----
        if (leader && elect1()) {
            u64 bd = mdesc(sb + SW0);
            for (int k = 0; k < 4; k++)
                tc_mma(d_hid, adesc + (u32)k * 2u, bd + (u32)k * 2u,
                       IDESC_N128, (u32)(k > 0));
            asm volatile(
                "tcgen05.commit.cta_group::1.mbarrier::arrive::one.shared::cluster.b64 [%0];"
                :: "r"(mbar) : "memory");
        }

        // ---- layers 1..5 ----
        for (int l = 1; l <= 5; l++) {
            mbar_wait_b(mbar, ph);
            ph ^= 1;
            asm volatile("tcgen05.fence::after_thread_sync;" ::: "memory");

            // epilogue of layer l-1: this warp's 64-col half (chunked, low regs)
            const u32 rowb = actb + (u32)half * 16384u + (u32)myrow * 128u;
            {
                u32 ra[32];
                LDTM_X32(ra, d_hid + (u32)half * 64u);
                asm volatile("tcgen05.wait::ld.sync.aligned;" ::: "memory");
                #pragma unroll
                for (int i = 0; i < 16; i++) {
                    u32 pk = rpack(__uint_as_float(ra[2 * i]),
                                   __uint_as_float(ra[2 * i + 1]));
                    asm volatile("st.shared.b32 [%0], %1;"
                        :: "r"(sb + swz(rowb + (u32)(2 * i) * 2u)), "r"(pk)
                        : "memory");
                }
                LDTM_X32(ra, d_hid + (u32)half * 64u + 32u);
                asm volatile("tcgen05.wait::ld.sync.aligned;" ::: "memory");
                #pragma unroll
                for (int i = 0; i < 16; i++) {
                    u32 pk = rpack(__uint_as_float(ra[2 * i]),
                                   __uint_as_float(ra[2 * i + 1]));
                    asm volatile("st.shared.b32 [%0], %1;"
                        :: "r"(sb + swz(rowb + (u32)(32 + 2 * i) * 2u)), "r"(pk)
                        : "memory");
                }
            }
            asm volatile("tcgen05.fence::before_thread_sync;" ::: "memory");
            asm volatile("fence.proxy.async.shared::cta;" ::: "memory");
            asm volatile("bar.sync %0, 256;" :: "r"(barid) : "memory");

            // MMA layer l
            if (leader && elect1()) {
                const u32 idesc = (l == 5) ? IDESC_N16 : IDESC_N128;
                const u32 bstr  = (l == 5) ? 128u : 1024u;
                const u32 dcol  = (l == 5) ? d_out : d_hid;
                u64 bd = mdesc(sb + WB[l]);
                for (int k = 0; k < 8; k++) {
                    u32 ao = (u32)(k & 3) * 2u + (u32)(k >> 2) * 1024u;
                    u32 bo = (u32)(k & 3) * 2u + (u32)(k >> 2) * bstr;
                    tc_mma(dcol, adesc + ao, bd + bo, idesc, (u32)(k > 0));
                }
                asm volatile(
                    "tcgen05.commit.cta_group::1.mbarrier::arrive::one.shared::cluster.b64 [%0];"
                    :: "r"(mbar) : "memory");
            }
        }

        // ---- output epilogue ----
        mbar_wait_b(mbar, ph);
        ph ^= 1;
        asm volatile("tcgen05.fence::after_thread_sync;" ::: "memory");
        if (half == 0) {
            u32 r16[16];
            LDTM_X16(r16, d_out);
            asm volatile("tcgen05.wait::ld.sync.aligned;" ::: "memory");
            if (probe) {
                asm volatile("st.shared.v4.b32 [%0], {%1,%2,%3,%4};"
                    :: "r"(sb + actb + (u32)myrow * 128u),
                       "r"(r16[0]), "r"(r16[1]), "r"(r16[2]), "r"(r16[3])
                    : "memory");
            } else {
                float* op = out + ((u64)t * 128u + (u64)myrow) * 16u;
                #pragma unroll
                for (int q = 0; q < 4; q++) {
                    float a0 = __uint_as_float(r16[4 * q])     + bz[4 * q];
                    float a1 = __uint_as_float(r16[4 * q + 1]) + bz[4 * q + 1];
                    float a2 = __uint_as_float(r16[4 * q + 2]) + bz[4 * q + 2];
                    float a3 = __uint_as_float(r16[4 * q + 3]) + bz[4 * q + 3];
                    asm volatile("st.global.v4.f32 [%0], {%1,%2,%3,%4};"
                        :: "l"(op + 4 * q), "f"(a0), "f"(a1), "f"(a2), "f"(a3)
                        : "memory");
                }
            }
        }
        // x buffer reuse is safe: layer-0 MMA long complete (mbar-ordered).
    }
    __syncthreads();
    if (tid < 32)
        asm volatile("tcgen05.dealloc.cta_group::1.sync.aligned.b32 %0, %1;"
                     :: "r"(tmem), "r"(512u));
}

extern "C" __global__ void __launch_bounds__(128, 1) tc_probe_basic()
{
    extern __shared__ char smem[];
    u32 sb;
    asm("{.reg .u64 t; cvta.to.shared.u64 t, %1; cvt.u32.u64 %0, t;}"
        : "=r"(sb) : "l"(smem));
    int tid = threadIdx.x, wid = tid >> 5;
    if (wid == 0) {
        asm volatile("tcgen05.alloc.cta_group::1.sync.aligned.shared::cta.b32 [%0], %1;"
                     :: "r"(sb), "r"(512u) : "memory");
        asm volatile("tcgen05.relinquish_alloc_permit.cta_group::1.sync.aligned;");
    }
    if (tid == 0) MBAR_INIT(sb + 8, 1);
    for (int i = tid; i < 8192; i += 128) {
        st_h(sb + SACT0 + (u32)i * 2u, 0.1f);
        st_h(sb + SW1 + (u32)i * 2u, 0.2f);
    }
    asm volatile("fence.proxy.async.shared::cta;" ::: "memory");
    __syncthreads();
    u32 tmem;
    asm volatile("ld.shared.b32 %0, [%1];" : "=r"(tmem) : "r"(sb));
    if (wid == 0 && elect1()) {
        tc_mma(tmem, mdesc(sb + SACT0), mdesc(sb + SW1), IDESC_N128, 0u);
        asm volatile(
            "tcgen05.commit.cta_group::1.mbarrier::arrive::one.shared::cluster.b64 [%0];"
            :: "r"(sb + 8) : "memory");
    }
    mbar_wait_b(sb + 8, 0);
    asm volatile("tcgen05.fence::after_thread_sync;" ::: "memory");
    u32 r[32];
    LDTM_X32(r, tmem);
    asm volatile("tcgen05.wait::ld.sync.aligned;" ::: "memory");
    asm volatile("st.shared.b32 [%0], %1;"
                 :: "r"(sb + SACT0 + (u32)tid * 4u), "r"(r[0]) : "memory");
    __syncthreads();
    if (wid == 0)
        asm volatile("tcgen05.dealloc.cta_group::1.sync.aligned.b32 %0, %1;"
                     :: "r"(tmem), "r"(512u));
}
)___";

#define TC_SMEM 218112
#define TC_NTILES 4096

static CUfunction g_tc_fn = nullptr;
static int g_tc_ok = 0;
static int g_sm = 148;

typedef CUresult (*PFN_cuInit)(unsigned int);
typedef CUresult (*PFN_cuDeviceGet)(CUdevice*, int);
typedef CUresult (*PFN_cuDeviceGetAttribute)(int*, CUdevice_attribute, CUdevice);
typedef CUresult (*PFN_cuDevicePrimaryCtxRetain)(CUcontext*, CUdevice);
typedef CUresult (*PFN_cuDevicePrimaryCtxReset)(CUdevice);
typedef CUresult (*PFN_cuCtxSetCurrent)(CUcontext);
typedef CUresult (*PFN_cuCtxSynchronize)(void);
typedef CUresult (*PFN_cuModuleLoadData)(CUmodule*, const void*);
typedef CUresult (*PFN_cuModuleGetFunction)(CUfunction*, CUmodule, const char*);
typedef CUresult (*PFN_cuFuncSetAttribute)(CUfunction, CUfunction_attribute, int);
typedef CUresult (*PFN_cuLaunchKernel)(CUfunction, unsigned, unsigned, unsigned,
                                       unsigned, unsigned, unsigned, unsigned,
                                       CUstream, void**, void**);
typedef nvrtcResult (*PFN_nvrtcCreateProgram)(nvrtcProgram*, const char*, const char*,
                                              int, const char* const*, const char* const*);
typedef nvrtcResult (*PFN_nvrtcCompileProgram)(nvrtcProgram, int, const char* const*);
typedef nvrtcResult (*PFN_nvrtcGetCUBINSize)(nvrtcProgram, size_t*);
typedef nvrtcResult (*PFN_nvrtcGetCUBIN)(nvrtcProgram, char*);
typedef nvrtcResult (*PFN_nvrtcGetProgramLogSize)(nvrtcProgram, size_t*);
typedef nvrtcResult (*PFN_nvrtcGetProgramLog)(nvrtcProgram, char*);

static PFN_cuLaunchKernel p_cuLaunchKernel = nullptr;

__attribute__((constructor))
static void _tc_ctor() {
    void* hc = dlopen("libcuda.so.1", RTLD_NOW | RTLD_GLOBAL);
    if (!hc) hc = dlopen("libcuda.so", RTLD_NOW | RTLD_GLOBAL);
    if (!hc) { fprintf(stderr, "[tc] no libcuda\n"); return; }
    void* hn = nullptr;
    const char* names[] = {"libnvrtc.so.13", "libnvrtc.so.12", "libnvrtc.so",
                           "/usr/local/cuda/lib64/libnvrtc.so", nullptr};
    for (int i = 0; names[i] && !hn; i++) hn = dlopen(names[i], RTLD_NOW | RTLD_GLOBAL);
    if (!hn) { fprintf(stderr, "[tc] no libnvrtc\n"); return; }

    PFN_cuInit f_cuInit = (PFN_cuInit)dlsym(hc, "cuInit");
    PFN_cuDeviceGet f_cuDeviceGet = (PFN_cuDeviceGet)dlsym(hc, "cuDeviceGet");
    PFN_cuDeviceGetAttribute f_cuDevAttr =
        (PFN_cuDeviceGetAttribute)dlsym(hc, "cuDeviceGetAttribute");
    PFN_cuDevicePrimaryCtxRetain f_cuRetain =
        (PFN_cuDevicePrimaryCtxRetain)dlsym(hc, "cuDevicePrimaryCtxRetain");
    PFN_cuDevicePrimaryCtxReset f_cuReset =
        (PFN_cuDevicePrimaryCtxReset)dlsym(hc, "cuDevicePrimaryCtxReset");
    PFN_cuCtxSetCurrent f_cuSetCur = (PFN_cuCtxSetCurrent)dlsym(hc, "cuCtxSetCurrent");
    PFN_cuCtxSynchronize f_cuSync = (PFN_cuCtxSynchronize)dlsym(hc, "cuCtxSynchronize");
    PFN_cuModuleLoadData f_cuModLoad = (PFN_cuModuleLoadData)dlsym(hc, "cuModuleLoadData");
    PFN_cuModuleGetFunction f_cuModFn =
        (PFN_cuModuleGetFunction)dlsym(hc, "cuModuleGetFunction");
    PFN_cuFuncSetAttribute f_cuFnAttr =
        (PFN_cuFuncSetAttribute)dlsym(hc, "cuFuncSetAttribute");
    p_cuLaunchKernel = (PFN_cuLaunchKernel)dlsym(hc, "cuLaunchKernel");
    PFN_nvrtcCreateProgram f_nCreate = (PFN_nvrtcCreateProgram)dlsym(hn, "nvrtcCreateProgram");
    PFN_nvrtcCompileProgram f_nCompile =
        (PFN_nvrtcCompileProgram)dlsym(hn, "nvrtcCompileProgram");
    PFN_nvrtcGetCUBINSize f_nCubSz = (PFN_nvrtcGetCUBINSize)dlsym(hn, "nvrtcGetCUBINSize");
    PFN_nvrtcGetCUBIN f_nCub = (PFN_nvrtcGetCUBIN)dlsym(hn, "nvrtcGetCUBIN");
    PFN_nvrtcGetProgramLogSize f_nLogSz =
        (PFN_nvrtcGetProgramLogSize)dlsym(hn, "nvrtcGetProgramLogSize");
    PFN_nvrtcGetProgramLog f_nLog = (PFN_nvrtcGetProgramLog)dlsym(hn, "nvrtcGetProgramLog");
    if (!f_cuInit || !f_cuDeviceGet || !f_cuRetain || !f_cuReset || !f_cuSetCur ||
        !f_cuSync || !f_cuModLoad || !f_cuModFn || !f_cuFnAttr || !p_cuLaunchKernel ||
        !f_nCreate || !f_nCompile || !f_nCubSz || !f_nCub) {
        fprintf(stderr, "[tc] dlsym missing\n"); return;
    }

    if (f_cuInit(0) != CUDA_SUCCESS) { fprintf(stderr, "[tc] cuInit fail\n"); return; }
    CUdevice dev; CUcontext ctx;
    if (f_cuDeviceGet(&dev, 0) != CUDA_SUCCESS) return;
    if (f_cuDevAttr) f_cuDevAttr(&g_sm, CU_DEVICE_ATTRIBUTE_MULTIPROCESSOR_COUNT, dev);
    if (f_cuRetain(&ctx, dev) != CUDA_SUCCESS) { fprintf(stderr, "[tc] ctx fail\n"); return; }
    f_cuSetCur(ctx);

    nvrtcProgram prog;
    if (f_nCreate(&prog, TC_SRC, "tc.cu", 0, nullptr, nullptr) != NVRTC_SUCCESS) return;
    const char* opts[] = {"--gpu-architecture=sm_103a"};
    nvrtcResult cr = f_nCompile(prog, 1, opts);
    if (cr != NVRTC_SUCCESS) {
        size_t lsz = 0;
        if (f_nLogSz && f_nLog && f_nLogSz(prog, &lsz) == NVRTC_SUCCESS && lsz > 1) {
            char* lg = (char*)malloc(lsz);
            f_nLog(prog, lg);
            fprintf(stderr, "[tc] nvrtc log: %.2000s\n", lg);
            free(lg);
        }
        return;
    }
    size_t isz = 0;
    if (f_nCubSz(prog, &isz) != NVRTC_SUCCESS || isz == 0) return;
    char* image = (char*)malloc(isz);
    if (f_nCub(prog, image) != NVRTC_SUCCESS) { free(image); return; }

    CUmodule mod; CUfunction fn = nullptr;
    if (f_cuModLoad(&mod, image) != CUDA_SUCCESS) {
        fprintf(stderr, "[tc] modload fail\n"); free(image); return;
    }
    if (f_cuModFn(&fn, mod, "mlp_tc") != CUDA_SUCCESS) { free(image); return; }
    f_cuFnAttr(fn, CU_FUNC_ATTRIBUTE_MAX_DYNAMIC_SHARED_SIZE_BYTES, TC_SMEM);

    void* zp = nullptr; int g2 = 2, nt = 8, pb = 1;
    void* prm[12] = {&zp, &zp, &zp, &zp, &zp, &zp, &zp, &zp, &zp, &g2, &nt, &pb};
    CUresult lr = p_cuLaunchKernel(fn, 2, 1, 1, 512, 1, 1, TC_SMEM,
                                   (CUstream)0, prm, nullptr);
    CUresult sr = (lr == CUDA_SUCCESS) ? f_cuSync() : lr;
    if (sr == CUDA_SUCCESS) {
        g_tc_fn = fn;
        g_tc_ok = 1;
        fprintf(stderr, "[tc] probe_full OK — 2-team split-epi tcgen05 live (sm=%d)\n", g_sm);
        free(image);
        return;
    }
    fprintf(stderr, "[tc] probe_full FAIL %d — resetting ctx, basic probe\n", (int)sr);
    f_cuReset(dev);

    if (f_cuRetain(&ctx, dev) == CUDA_SUCCESS) {
        f_cuSetCur(ctx);
        CUmodule mod2; CUfunction fb = nullptr;
        if (f_cuModLoad(&mod2, image) == CUDA_SUCCESS &&
            f_cuModFn(&fb, mod2, "tc_probe_basic") == CUDA_SUCCESS) {
            f_cuFnAttr(fb, CU_FUNC_ATTRIBUTE_MAX_DYNAMIC_SHARED_SIZE_BYTES, TC_SMEM);
            CUresult l2 = p_cuLaunchKernel(fb, 1, 1, 1, 128, 1, 1, TC_SMEM,
                                           (CUstream)0, nullptr, nullptr);
            CUresult s2 = (l2 == CUDA_SUCCESS) ? f_cuSync() : l2;
            fprintf(stderr, "[tc] probe_basic result: %d\n", (int)s2);
        } else {
            fprintf(stderr, "[tc] probe_basic load fail\n");
        }
        f_cuReset(dev);
    }
    free(image);
    g_tc_ok = 0;
}

// ============================================================================
// Fallback: proven R7 HMMA kernel (182.8 us).
// ============================================================================
#define NSAMP   524288
#define MTILE   256
#define NTILES  (NSAMP / MTILE)
#define NTHREADS 512
#define DIMO    16
#define SW0   0
#define SW1   16384
#define SW2   49152
#define SW3   81920
#define SW4   114688
#define SW5   147456
#define SX    153600
#define XSTR  144
#define SMEM_TOTAL (SX + 256 * XSTR)

__device__ __forceinline__ uint32_t smem_u32(const void* p) {
    uint32_t a;
    asm("{ .reg .u64 t; cvta.to.shared.u64 t, %1; cvt.u32.u64 %0, t; }"
        : "=r"(a) : "l"(p));
    return a;
}
__device__ __forceinline__ void ldsm_x4(uint32_t* r, uint32_t addr) {
    asm volatile("ldmatrix.sync.aligned.m8n8.x4.shared.b16 {%0,%1,%2,%3}, [%4];"
                 : "=r"(r[0]), "=r"(r[1]), "=r"(r[2]), "=r"(r[3]) : "r"(addr));
}
__device__ __forceinline__ void ldsm_x4t(uint32_t* r, uint32_t addr) {
    asm volatile("ldmatrix.sync.aligned.m8n8.x4.trans.shared.b16 {%0,%1,%2,%3}, [%4];"
                 : "=r"(r[0]), "=r"(r[1]), "=r"(r[2]), "=r"(r[3]) : "r"(addr));
}
__device__ __forceinline__ void mma16816(float* c, const uint32_t* a,
                                         uint32_t b0, uint32_t b1) {
    asm volatile(
        "mma.sync.aligned.m16n8k16.row.col.f32.f16.f16.f32 "
        "{%0,%1,%2,%3}, {%4,%5,%6,%7}, {%8,%9}, {%0,%1,%2,%3};"
        : "+f"(c[0]), "+f"(c[1]), "+f"(c[2]), "+f"(c[3])
        : "r"(a[0]), "r"(a[1]), "r"(a[2]), "r"(a[3]), "r"(b0), "r"(b1));
}
__device__ __forceinline__ void mma16816_z(float* c, const uint32_t* a,
                                           uint32_t b0, uint32_t b1) {
    asm volatile(
        "mma.sync.aligned.m16n8k16.row.col.f32.f16.f16.f32 "
        "{%0,%1,%2,%3}, {%4,%5,%6,%7}, {%8,%9}, {%10,%10,%10,%10};"
        : "=f"(c[0]), "=f"(c[1]), "=f"(c[2]), "=f"(c[3])
        : "r"(a[0]), "r"(a[1]), "r"(a[2]), "r"(a[3]), "r"(b0), "r"(b1),
          "f"(0.0f));
}
__device__ __forceinline__ uint32_t relu_pack(float a, float b) {
    __half2 h = __floats2half2_rn(a, b);
    h = __hmax2(h, __floats2half2_rn(0.0f, 0.0f));
    return *(uint32_t*)&h;
}

__global__ void __launch_bounds__(NTHREADS, 1)
mlp_chain2_kernel(const float* __restrict__ x,
                  const float* __restrict__ gW0, const float* __restrict__ gW1,
                  const float* __restrict__ gW2, const float* __restrict__ gW3,
                  const float* __restrict__ gW4, const float* __restrict__ gW5,
                  const float* __restrict__ bias,
                  float* __restrict__ out) {
    extern __shared__ char smem[];
    const uint32_t sb = smem_u32(smem);
    const int tid  = threadIdx.x;
    const int wid  = tid >> 5;
    const int lane = tid & 31;

    {
        const float* gws[5] = {gW0, gW1, gW2, gW3, gW4};
        const uint32_t so[5] = {SW0, SW1, SW2, SW3, SW4};
        const int rows[5] = {64, 128, 128, 128, 128};
        #pragma unroll
        for (int w = 0; w < 5; w++) {
            for (int i = tid; i < rows[w] * 32; i += NTHREADS) {
                int k = i >> 5, n4 = i & 31;
                float4 v = ((const float4*)gws[w])[i];
                __half2 h0 = __floats2half2_rn(v.x, v.y), h1 = __floats2half2_rn(v.z, v.w);
                uint2 p = make_uint2(*(uint32_t*)&h0, *(uint32_t*)&h1);
                int c = n4 >> 1;
                int swc = (c & 8) | ((c ^ (k & 7)) & 7);
                *(uint2*)(smem + so[w] + k * 256 + swc * 16 + (n4 & 1) * 8) = p;
            }
        }
    }
    for (int i = tid; i < 128 * 4; i += NTHREADS) {
        int k = i >> 2, n4 = i & 3;
        float4 v = ((const float4*)gW5)[i];
        __half2 h0 = __floats2half2_rn(v.x, v.y), h1 = __floats2half2_rn(v.z, v.w);
        uint2 p = make_uint2(*(uint32_t*)&h0, *(uint32_t*)&h1);
        *(uint2*)(smem + SW5 + k * 48 + n4 * 8) = p;
    }

    const int col0 = (lane & 3) * 2;
    const int row0 = lane >> 2;
    float bz0 = __ldg(bias + col0);
    float bz1 = __ldg(bias + col0 + 1);
    float bz2 = __ldg(bias + 8 + col0);
    float bz3 = __ldg(bias + 9 + col0);

    __syncthreads();

    const int lrow = lane & 15;
    const int lhi  = lane >> 4;
    const int lr7  = lrow & 7;
    const uint32_t aA = sb + SX + (16 * wid + lrow) * XSTR + lhi * 16;
    const uint32_t w5a = sb + SW5 + (uint32_t)lrow * 48 + lhi * 16;
    const uint32_t xsts_row = SX + 16 * wid * XSTR;

    uint32_t joff[8];
    #pragma unroll
    for (int j = 0; j < 8; j++) {
        int c = 2 * j + lhi;
        int swc = (c & 8) | ((c ^ lr7) & 7);
        joff[j] = (uint32_t)lrow * 256 + swc * 16;
    }

    const int G = gridDim.x;
    {
        const float4* xg = (const float4*)(x + (size_t)blockIdx.x * MTILE * 64)
                         + wid * 256;
        #pragma unroll
        for (int it = 0; it < 8; it++) {
            int idx = lane + it * 32;
            int r = idx >> 4, c4 = idx & 15;
            float4 v = xg[idx];
            __half2 h0 = __floats2half2_rn(v.x, v.y), h1 = __floats2half2_rn(v.z, v.w);
            uint2 p = make_uint2(*(uint32_t*)&h0, *(uint32_t*)&h1);
            *(uint2*)(smem + xsts_row + r * XSTR + c4 * 8) = p;
        }
    }

    for (int t = blockIdx.x; t < NTILES; t += G) {
        __syncwarp();
        uint32_t A[8][4];
        #pragma unroll
        for (int kb = 0; kb < 4; kb++) ldsm_x4(A[kb], aA + kb * 32);

        float C[16][4];
        #pragma unroll
        for (int j = 0; j < 8; j++) {
            uint32_t B[4];
            ldsm_x4t(B, sb + SW0 + joff[j]);
            mma16816_z(C[2 * j],     A[0], B[0], B[1]);
            mma16816_z(C[2 * j + 1], A[0], B[2], B[3]);
        }
        #pragma unroll
        for (int kb = 1; kb < 4; kb++)
            #pragma unroll
            for (int j = 0; j < 8; j++) {
                uint32_t B[4];
                ldsm_x4t(B, sb + SW0 + kb * 4096 + joff[j]);
                mma16816(C[2 * j],     A[kb], B[0], B[1]);
                mma16816(C[2 * j + 1], A[kb], B[2], B[3]);
            }

        const int tn = t + G;
        const bool pf = tn < NTILES;
        const float4* xgn = (const float4*)(x + (size_t)tn * MTILE * 64) + wid * 256;
        float4 vb[4];
        if (pf) {
            #pragma unroll
            for (int it = 0; it < 4; it++) vb[it] = xgn[lane + it * 32];
        }

        const uint32_t WS[4] = {SW1, SW2, SW3, SW4};
        #pragma unroll
        for (int l = 0; l < 4; l++) {
            #pragma unroll
            for (int j = 0; j < 8; j++) {
                A[j][0] = relu_pack(C[2 * j][0],     C[2 * j][1]);
                A[j][1] = relu_pack(C[2 * j][2],     C[2 * j][3]);
                A[j][2] = relu_pack(C[2 * j + 1][0], C[2 * j + 1][1]);
                A[j][3] = relu_pack(C[2 * j + 1][2], C[2 * j + 1][3]);
            }
            const uint32_t wb = sb + WS[l];
            #pragma unroll
            for (int j = 0; j < 8; j++) {
                uint32_t B[4];
                ldsm_x4t(B, wb + joff[j]);
                mma16816_z(C[2 * j],     A[0], B[0], B[1]);
                mma16816_z(C[2 * j + 1], A[0], B[2], B[3]);
            }
            #pragma unroll
            for (int kb = 1; kb < 8; kb++)
                #pragma unroll
                for (int j = 0; j < 8; j++) {
                    uint32_t B[4];
                    ldsm_x4t(B, wb + kb * 4096 + joff[j]);
                    mma16816(C[2 * j],     A[kb], B[0], B[1]);
                    mma16816(C[2 * j + 1], A[kb], B[2], B[3]);
                }
            if (l == 0 && pf) {
                #pragma unroll
                for (int it = 0; it < 4; it++) {
                    int idx = lane + it * 32;
                    int r = idx >> 4, c4 = idx & 15;
                    __half2 h0 = __floats2half2_rn(vb[it].x, vb[it].y);
                    __half2 h1 = __floats2half2_rn(vb[it].z, vb[it].w);
                    uint2 p = make_uint2(*(uint32_t*)&h0, *(uint32_t*)&h1);
                    *(uint2*)(smem + xsts_row + r * XSTR + c4 * 8) = p;
                }
                #pragma unroll
                for (int it = 0; it < 4; it++) vb[it] = xgn[lane + (it + 4) * 32];
            }
            if (l == 1 && pf) {
                #pragma unroll
                for (int it = 0; it < 4; it++) {
                    int idx = lane + (it + 4) * 32;
                    int r = idx >> 4, c4 = idx & 15;
                    __half2 h0 = __floats2half2_rn(vb[it].x, vb[it].y);
                    __half2 h1 = __floats2half2_rn(vb[it].z, vb[it].w);
                    uint2 p = make_uint2(*(uint32_t*)&h0, *(uint32_t*)&h1);
                    *(uint2*)(smem + xsts_row + r * XSTR + c4 * 8) = p;
                }
            }
        }

        #pragma unroll
        for (int j = 0; j < 8; j++) {
            A[j][0] = relu_pack(C[2 * j][0],     C[2 * j][1]);
            A[j][1] = relu_pack(C[2 * j][2],     C[2 * j][3]);
            A[j][2] = relu_pack(C[2 * j + 1][0], C[2 * j + 1][1]);
            A[j][3] = relu_pack(C[2 * j + 1][2], C[2 * j + 1][3]);
        }
        float C5[2][4];
        {
            uint32_t B[4];
            ldsm_x4t(B, w5a);
            mma16816_z(C5[0], A[0], B[0], B[1]);
            mma16816_z(C5[1], A[0], B[2], B[3]);
        }
        #pragma unroll
        for (int kb = 1; kb < 8; kb++) {
            uint32_t B[4];
            ldsm_x4t(B, w5a + kb * 768);
            mma16816(C5[0], A[kb], B[0], B[1]);
            mma16816(C5[1], A[kb], B[2], B[3]);
        }

        const size_t g0 = ((size_t)t * MTILE + 16 * wid + row0) * DIMO;
        const size_t g1 = g0 + 8 * DIMO;
        float2 v;
        v.x = C5[0][0] + bz0; v.y = C5[0][1] + bz1;
        *(float2*)(out + g0 + col0) = v;
        v.x = C5[1][0] + bz2; v.y = C5[1][1] + bz3;
        *(float2*)(out + g0 + 8 + col0) = v;
        v.x = C5[0][2] + bz0; v.y = C5[0][3] + bz1;
        *(float2*)(out + g1 + col0) = v;
        v.x = C5[1][2] + bz2; v.y = C5[1][3] + bz3;
        *(float2*)(out + g1 + 8 + col0) = v;
    }
}

static CUstream _pick_stream() {
    cudaStreamCaptureStatus s = cudaStreamCaptureStatusNone;
    if (cudaStreamIsCapturing((cudaStream_t)0x2, &s) == cudaSuccess &&
        s == cudaStreamCaptureStatusActive)
        return (CUstream)0x2;
    s = cudaStreamCaptureStatusNone;
    if (cudaStreamIsCapturing((cudaStream_t)0x1, &s) == cudaSuccess &&
        s == cudaStreamCaptureStatusActive)
        return (CUstream)0x1;
#ifdef CUDA_API_PER_THREAD_DEFAULT_STREAM
    return (CUstream)0x2;
#else
    return (CUstream)0x1;
#endif
}

extern "C" void kernel_launch(void* const* d_in, const int* in_sizes, int n_in,
                              void* d_out, int out_size) {
    const float* x    = (const float*)d_in[0];
    const float* W0   = (const float*)d_in[1];
    const float* W1   = (const float*)d_in[2];
    const float* W2   = (const float*)d_in[3];
    const float* W3   = (const float*)d_in[4];
    const float* W4   = (const float*)d_in[5];
    const float* W5   = (const float*)d_in[6];
    const float* bias = (const float*)d_in[7];
    float* out = (float*)d_out;

    if (g_tc_ok && g_tc_fn && p_cuLaunchKernel) {
        int grid = g_sm, ntiles = TC_NTILES, probe = 0;
        void* params[12] = {(void*)&x, (void*)&W0, (void*)&W1, (void*)&W2,
                            (void*)&W3, (void*)&W4, (void*)&W5, (void*)&bias,
                            (void*)&out, (void*)&grid, (void*)&ntiles,
                            (void*)&probe};
        CUresult r = p_cuLaunchKernel(g_tc_fn, (unsigned)grid, 1, 1, 512, 1, 1,
                                      TC_SMEM, _pick_stream(), params, nullptr);
        if (r == CUDA_SUCCESS) return;
        fprintf(stderr, "[tc] real launch fail %d — falling back\n", (int)r);
        g_tc_ok = 0;
    }

    cudaFuncSetAttribute(mlp_chain2_kernel,
                         cudaFuncAttributeMaxDynamicSharedMemorySize, SMEM_TOTAL);
    int sm = 148;
    cudaDeviceGetAttribute(&sm, cudaDevAttrMultiProcessorCount, 0);
    int grid = sm < NTILES ? sm : NTILES;
    mlp_chain2_kernel<<<grid, NTHREADS, SMEM_TOTAL>>>(x, W0, W1, W2, W3, W4, W5,
                                                      bias, out);
}

// round 14
// speedup vs baseline: 1.6958x; 1.3915x over previous
#include <cuda_runtime.h>
#include <cuda_fp16.h>
#include <cuda.h>
#include <nvrtc.h>
#include <dlfcn.h>
#include <cstdio>
#include <cstdlib>
#include <cstring>
#include <cstdint>

// ============================================================================
// Embedded tcgen05 kernel (NVRTC, --gpu-architecture=sm_103a).
// TWO independent 8-warp teams; activations live ENTIRELY in TMEM:
//   epilogue: LDTM (fp32 accum) -> relu fp16x2 -> STTM into TMEM A-region
//   MMA: TS-mode (A in TMEM, B = weights in SMEM). SMEM holds weights only.
// probe=1 keeps identical instruction structure with global accesses guarded.
// ============================================================================
static const char* TC_SRC = R"___(
typedef unsigned int u32;
typedef unsigned long long u64;

#define SW0   1024u
#define SW1   17408u
#define SW2   50176u
#define SW3   82944u
#define SW4   115712u
#define SW5   148480u
#define IDESC_N128 ((1u<<4) | (16u<<17) | (8u<<24))
#define IDESC_N16  ((1u<<4) | ( 2u<<17) | (8u<<24))

__device__ __forceinline__ u32 swz(u32 o) { return o ^ ((o >> 3) & 0x70u); }

__device__ __forceinline__ u64 mdesc(u32 addr) {
    return ((u64)2 << 61) | ((u64)1 << 46) | ((u64)64 << 32) | ((u64)1 << 16)
         | ((u64)(addr >> 4) & 0x3FFFu);
}
__device__ __forceinline__ void st_h(u32 a, float v) {
    asm volatile("{.reg .b16 h; cvt.rn.f16.f32 h, %1; st.shared.b16 [%0], h;}"
                 :: "r"(a), "f"(v) : "memory");
}
__device__ __forceinline__ u32 rpack(float a, float b) {
    u32 r;
    asm("cvt.rn.f16x2.f32 %0, %1, %2;" : "=r"(r) : "f"(b), "f"(a));
    asm("max.f16x2 %0, %0, %1;" : "+r"(r) : "r"(0u));
    return r;
}
__device__ __forceinline__ u32 cpack(float a, float b) {   // pack, no relu (x)
    u32 r;
    asm("cvt.rn.f16x2.f32 %0, %1, %2;" : "=r"(r) : "f"(b), "f"(a));
    return r;
}
// TS-mode f16 MMA: A in TMEM, B in SMEM.
__device__ __forceinline__ void tc_mma_ts(u32 d, u32 a, u64 b, u32 id, u32 en) {
    asm volatile("{.reg .pred p; setp.ne.u32 p, %4, 0;\n\t"
        "tcgen05.mma.cta_group::1.kind::f16 [%0], [%1], %2, %3, {%5,%5,%5,%5}, p;}"
        :: "r"(d), "r"(a), "l"(b), "r"(id), "r"(en), "r"(0u) : "memory");
}
// SS-mode (kept for basic probe only)
__device__ __forceinline__ void tc_mma(u32 d, u64 a, u64 b, u32 id, u32 en) {
    asm volatile("{.reg .pred p; setp.ne.u32 p, %4, 0;\n\t"
        "tcgen05.mma.cta_group::1.kind::f16 [%0], %1, %2, %3, {%5,%5,%5,%5}, p;}"
        :: "r"(d), "l"(a), "l"(b), "r"(id), "r"(en), "r"(0u) : "memory");
}
__device__ __forceinline__ bool elect1() {
    u32 p;
    asm volatile("{.reg .pred p; elect.sync _|p, 0xFFFFFFFF; selp.b32 %0,1,0,p;}"
                 : "=r"(p));
    return p != 0;
}
#define MBAR_INIT(mb, c) \
    asm volatile("mbarrier.init.shared.b64 [%0], %1;" \
        :: "r"((u32)(mb)), "r"((u32)(c)) : "memory")
__device__ __forceinline__ void mbar_wait_b(u32 mb, u32 par) {
    for (int i = 0; i < 4096; i++) {
        u32 d;
        asm volatile("{.reg .pred p;\n\t"
            "mbarrier.try_wait.parity.acquire.cta.shared::cta.b64 p, [%1], %2, 0x989680;\n\t"
            "selp.b32 %0,1,0,p;}" : "=r"(d) : "r"(mb), "r"(par) : "memory");
        if (d) return;
    }
}
#define LDTM_X32(r, a) \
    asm volatile("tcgen05.ld.sync.aligned.32x32b.x32.b32 " \
        "{%0,%1,%2,%3,%4,%5,%6,%7,%8,%9,%10,%11,%12,%13,%14,%15," \
        "%16,%17,%18,%19,%20,%21,%22,%23,%24,%25,%26,%27,%28,%29,%30,%31}, [%32];" \
        : "=r"((r)[0]),"=r"((r)[1]),"=r"((r)[2]),"=r"((r)[3]), \
          "=r"((r)[4]),"=r"((r)[5]),"=r"((r)[6]),"=r"((r)[7]), \
          "=r"((r)[8]),"=r"((r)[9]),"=r"((r)[10]),"=r"((r)[11]), \
          "=r"((r)[12]),"=r"((r)[13]),"=r"((r)[14]),"=r"((r)[15]), \
          "=r"((r)[16]),"=r"((r)[17]),"=r"((r)[18]),"=r"((r)[19]), \
          "=r"((r)[20]),"=r"((r)[21]),"=r"((r)[22]),"=r"((r)[23]), \
          "=r"((r)[24]),"=r"((r)[25]),"=r"((r)[26]),"=r"((r)[27]), \
          "=r"((r)[28]),"=r"((r)[29]),"=r"((r)[30]),"=r"((r)[31]) \
        : "r"(a))
#define LDTM_X16(r, a) \
    asm volatile("tcgen05.ld.sync.aligned.32x32b.x16.b32 " \
        "{%0,%1,%2,%3,%4,%5,%6,%7,%8,%9,%10,%11,%12,%13,%14,%15}, [%16];" \
        : "=r"((r)[0]),"=r"((r)[1]),"=r"((r)[2]),"=r"((r)[3]), \
          "=r"((r)[4]),"=r"((r)[5]),"=r"((r)[6]),"=r"((r)[7]), \
          "=r"((r)[8]),"=r"((r)[9]),"=r"((r)[10]),"=r"((r)[11]), \
          "=r"((r)[12]),"=r"((r)[13]),"=r"((r)[14]),"=r"((r)[15]) \
        : "r"(a))
#define STTM_X16(a, r) \
    asm volatile("tcgen05.st.sync.aligned.32x32b.x16.b32 [%0], " \
        "{%1,%2,%3,%4,%5,%6,%7,%8,%9,%10,%11,%12,%13,%14,%15,%16};" \
        :: "r"(a), \
           "r"((r)[0]),"r"((r)[1]),"r"((r)[2]),"r"((r)[3]), \
           "r"((r)[4]),"r"((r)[5]),"r"((r)[6]),"r"((r)[7]), \
           "r"((r)[8]),"r"((r)[9]),"r"((r)[10]),"r"((r)[11]), \
           "r"((r)[12]),"r"((r)[13]),"r"((r)[14]),"r"((r)[15]) \
        : "memory")
#define TC_WAIT_LD() asm volatile("tcgen05.wait::ld.sync.aligned;" ::: "memory")
#define TC_WAIT_ST() asm volatile("tcgen05.wait::st.sync.aligned;" ::: "memory")
#define TC_FENCE_B() asm volatile("tcgen05.fence::before_thread_sync;" ::: "memory")
#define TC_FENCE_A() asm volatile("tcgen05.fence::after_thread_sync;" ::: "memory")

extern "C" __global__ void __launch_bounds__(512, 1)
mlp_tc(const float* x, const float* gW0, const float* gW1, const float* gW2,
       const float* gW3, const float* gW4, const float* gW5,
       const float* bias, float* out, int grid, int ntiles, int probe)
{
    extern __shared__ char smem[];
    u32 sb;
    asm("{.reg .u64 t; cvta.to.shared.u64 t, %1; cvt.u32.u64 %0, t;}"
        : "=r"(sb) : "l"(smem));
    const int tid  = threadIdx.x;
    const int lane = tid & 31;
    const int team = tid >> 8;
    const int ttid = tid & 255;
    const int twid = ttid >> 5;
    const int sub  = twid & 3;            // TMEM subpartition (= global wid % 4)
    const int half = (twid >> 2) & 1;     // column half owned by this warp
    const int myrow = sub * 32 + lane;
    const u32 woff = (u32)sub << 21;      // STTM subpartition address offset

    if (tid < 32) {
        asm volatile("tcgen05.alloc.cta_group::1.sync.aligned.shared::cta.b32 [%0], %1;"
                     :: "r"(sb), "r"(512u) : "memory");
        asm volatile("tcgen05.relinquish_alloc_permit.cta_group::1.sync.aligned;");
    }
    if (tid == 0) { MBAR_INIT(sb + 8, 1); MBAR_INIT(sb + 16, 1); }

    // ---- weights -> fp16 SMEM, [N rows x K cols] SW128 blocked-atom ----
    {
        const float* gws[4] = {gW1, gW2, gW3, gW4};
        const u32 so[4] = {SW1, SW2, SW3, SW4};
        for (int w = 0; w < 4; w++)
            for (int i = tid; i < 128 * 128; i += 512) {
                int k = i >> 7, n = i & 127;
                u32 off = (u32)(k >> 6) * 16384u + (u32)n * 128u + (u32)(k & 63) * 2u;
                float v = probe ? 0.03f : gws[w][i];
                st_h(sb + so[w] + swz(off), v);
            }
    }
    for (int i = tid; i < 64 * 128; i += 512) {
        int k = i >> 7, n = i & 127;
        u32 off = (u32)n * 128u + (u32)k * 2u;
        float v = probe ? 0.02f : gW0[i];
        st_h(sb + SW0 + swz(off), v);
    }
    for (int i = tid; i < 128 * 16; i += 512) {
        int k = i >> 4, n = i & 15;
        u32 off = (u32)(k >> 6) * 2048u + (u32)n * 128u + (u32)(k & 63) * 2u;
        float v = probe ? 0.01f : gW5[i];
        st_h(sb + SW5 + swz(off), v);
    }
    float bz[16];
    for (int i = 0; i < 16; i++) bz[i] = probe ? 0.0f : bias[i];

    asm volatile("fence.proxy.async.shared::cta;" ::: "memory");
    __syncthreads();
    u32 tmem;
    asm volatile("ld.shared.b32 %0, [%1];" : "=r"(tmem) : "r"(sb));

    // TMEM layout: hid accum team0 @0, team1 @128; A region team0 @256,
    // team1 @320 (64 cols each); out team0 @384, team1 @400.
    const u32 d_hid = tmem + (u32)team * 128u;
    const u32 aT    = tmem + 256u + (u32)team * 64u;
    const u32 d_out = tmem + 384u + (u32)team * 16u;
    const u32 mbar  = sb + 8u + 8u * (u32)team;
    const int barid = team + 1;
    const bool leader = (twid == 0);
    const u32 WB[6] = {SW0, SW1, SW2, SW3, SW4, SW5};

    u32 ph = 0;

    for (int t = blockIdx.x * 2 + team; t < ntiles; t += 2 * grid) {
        // ---- x: each thread loads its row-half [32 floats] -> STTM (K=64) ----
        {
            u32 pk[16];
            if (probe) {
                #pragma unroll
                for (int i = 0; i < 16; i++)
                    pk[i] = cpack(0.05f * (float)(i & 7), 0.2f);
            } else {
                const float* xr = x + ((u64)t * 128u + (u64)myrow) * 64u
                                + (u64)half * 32u;
                #pragma unroll
                for (int i = 0; i < 8; i++) {
                    float vx, vy, vz, vw;
                    asm("ld.global.nc.v4.f32 {%0,%1,%2,%3}, [%4];"
                        : "=f"(vx), "=f"(vy), "=f"(vz), "=f"(vw)
                        : "l"(xr + 4 * i));
                    pk[2 * i]     = cpack(vx, vy);
                    pk[2 * i + 1] = cpack(vz, vw);
                }
            }
            // layer-0 A: 32 cols total; this warp owns cols half*16..+15
            STTM_X16(aT + (u32)half * 16u + woff, pk);
            TC_WAIT_ST();
        }
        TC_FENCE_B();
        asm volatile("bar.sync %0, 256;" :: "r"(barid) : "memory");

        // ---- layer 0 MMA: TS-mode, K=64 ----
        if (leader && elect1()) {
            TC_FENCE_A();
            u64 bd = mdesc(sb + SW0);
            for (int k = 0; k < 4; k++)
                tc_mma_ts(d_hid, aT + (u32)k * 8u, bd + (u32)k * 2u,
                          IDESC_N128, (u32)(k > 0));
            asm volatile(
                "tcgen05.commit.cta_group::1.mbarrier::arrive::one.shared::cluster.b64 [%0];"
                :: "r"(mbar) : "memory");
        }

        // ---- layers 1..5 ----
        for (int l = 1; l <= 5; l++) {
            mbar_wait_b(mbar, ph);
            ph ^= 1;
            TC_FENCE_A();

            // epilogue of layer l-1: LDTM -> relu fp16x2 -> STTM into A region.
            // This warp's 64 accum cols -> 32 A cols at aT + half*32.
            {
                u32 ra[32], pk[16];
                LDTM_X32(ra, d_hid + (u32)half * 64u);
                TC_WAIT_LD();
                #pragma unroll
                for (int i = 0; i < 16; i++)
                    pk[i] = rpack(__uint_as_float(ra[2 * i]),
                                  __uint_as_float(ra[2 * i + 1]));
                STTM_X16(aT + (u32)half * 32u + woff, pk);
                LDTM_X32(ra, d_hid + (u32)half * 64u + 32u);
                TC_WAIT_LD();
                #pragma unroll
                for (int i = 0; i < 16; i++)
                    pk[i] = rpack(__uint_as_float(ra[2 * i]),
                                  __uint_as_float(ra[2 * i + 1]));
                STTM_X16(aT + (u32)half * 32u + 16u + woff, pk);
                TC_WAIT_ST();
            }
            TC_FENCE_B();
            asm volatile("bar.sync %0, 256;" :: "r"(barid) : "memory");

            // MMA layer l: TS-mode, K=128
            if (leader && elect1()) {
                TC_FENCE_A();
                const u32 idesc = (l == 5) ? IDESC_N16 : IDESC_N128;
                const u32 bstr  = (l == 5) ? 128u : 1024u;
                const u32 dcol  = (l == 5) ? d_out : d_hid;
                u64 bd = mdesc(sb + WB[l]);
                for (int k = 0; k < 8; k++) {
                    u32 bo = (u32)(k & 3) * 2u + (u32)(k >> 2) * bstr;
                    tc_mma_ts(dcol, aT + (u32)k * 8u, bd + bo, idesc,
                              (u32)(k > 0));
                }
                asm volatile(
                    "tcgen05.commit.cta_group::1.mbarrier::arrive::one.shared::cluster.b64 [%0];"
                    :: "r"(mbar) : "memory");
            }
        }

        // ---- output epilogue ----
        mbar_wait_b(mbar, ph);
        ph ^= 1;
        TC_FENCE_A();
        if (half == 0) {
            u32 r16[16];
            LDTM_X16(r16, d_out);
            TC_WAIT_LD();
            if (!probe) {
                float* op = out + ((u64)t * 128u + (u64)myrow) * 16u;
                #pragma unroll
                for (int q = 0; q < 4; q++) {
                    float a0 = __uint_as_float(r16[4 * q])     + bz[4 * q];
                    float a1 = __uint_as_float(r16[4 * q + 1]) + bz[4 * q + 1];
                    float a2 = __uint_as_float(r16[4 * q + 2]) + bz[4 * q + 2];
                    float a3 = __uint_as_float(r16[4 * q + 3]) + bz[4 * q + 3];
                    asm volatile("st.global.v4.f32 [%0], {%1,%2,%3,%4};"
                        :: "l"(op + 4 * q), "f"(a0), "f"(a1), "f"(a2), "f"(a3)
                        : "memory");
                }
            }
        }
        // A-region reuse next tile is safe: layer-5 MMA completed (mbar).
    }
    __syncthreads();
    if (tid < 32)
        asm volatile("tcgen05.dealloc.cta_group::1.sync.aligned.b32 %0, %1;"
                     :: "r"(tmem), "r"(512u));
}

extern "C" __global__ void __launch_bounds__(128, 1) tc_probe_basic()
{
    extern __shared__ char smem[];
    u32 sb;
    asm("{.reg .u64 t; cvta.to.shared.u64 t, %1; cvt.u32.u64 %0, t;}"
        : "=r"(sb) : "l"(smem));
    int tid = threadIdx.x, wid = tid >> 5;
    if (wid == 0) {
        asm volatile("tcgen05.alloc.cta_group::1.sync.aligned.shared::cta.b32 [%0], %1;"
                     :: "r"(sb), "r"(512u) : "memory");
        asm volatile("tcgen05.relinquish_alloc_permit.cta_group::1.sync.aligned;");
    }
    if (tid == 0) MBAR_INIT(sb + 8, 1);
    for (int i = tid; i < 8192; i += 128) {
        st_h(sb + SW0 + (u32)i * 2u, 0.1f);
        st_h(sb + SW1 + (u32)i * 2u, 0.2f);
    }
    asm volatile("fence.proxy.async.shared::cta;" ::: "memory");
    __syncthreads();
    u32 tmem;
    asm volatile("ld.shared.b32 %0, [%1];" : "=r"(tmem) : "r"(sb));
    if (wid == 0 && elect1()) {
        tc_mma(tmem, mdesc(sb + SW0), mdesc(sb + SW1), IDESC_N128, 0u);
        asm volatile(
            "tcgen05.commit.cta_group::1.mbarrier::arrive::one.shared::cluster.b64 [%0];"
            :: "r"(sb + 8) : "memory");
    }
    mbar_wait_b(sb + 8, 0);
    TC_FENCE_A();
    u32 r[32];
    LDTM_X32(r, tmem);
    TC_WAIT_LD();
    asm volatile("st.shared.b32 [%0], %1;"
                 :: "r"(sb + SW0 + (u32)tid * 4u), "r"(r[0]) : "memory");
    __syncthreads();
    if (wid == 0)
        asm volatile("tcgen05.dealloc.cta_group::1.sync.aligned.b32 %0, %1;"
                     :: "r"(tmem), "r"(512u));
}
)___";

#define TC_SMEM 153600
#define TC_NTILES 4096

static CUfunction g_tc_fn = nullptr;
static int g_tc_ok = 0;
static int g_sm = 148;

typedef CUresult (*PFN_cuInit)(unsigned int);
typedef CUresult (*PFN_cuDeviceGet)(CUdevice*, int);
typedef CUresult (*PFN_cuDeviceGetAttribute)(int*, CUdevice_attribute, CUdevice);
typedef CUresult (*PFN_cuDevicePrimaryCtxRetain)(CUcontext*, CUdevice);
typedef CUresult (*PFN_cuDevicePrimaryCtxReset)(CUdevice);
typedef CUresult (*PFN_cuCtxSetCurrent)(CUcontext);
typedef CUresult (*PFN_cuCtxSynchronize)(void);
typedef CUresult (*PFN_cuModuleLoadData)(CUmodule*, const void*);
typedef CUresult (*PFN_cuModuleGetFunction)(CUfunction*, CUmodule, const char*);
typedef CUresult (*PFN_cuFuncSetAttribute)(CUfunction, CUfunction_attribute, int);
typedef CUresult (*PFN_cuLaunchKernel)(CUfunction, unsigned, unsigned, unsigned,
                                       unsigned, unsigned, unsigned, unsigned,
                                       CUstream, void**, void**);
typedef nvrtcResult (*PFN_nvrtcCreateProgram)(nvrtcProgram*, const char*, const char*,
                                              int, const char* const*, const char* const*);
typedef nvrtcResult (*PFN_nvrtcCompileProgram)(nvrtcProgram, int, const char* const*);
typedef nvrtcResult (*PFN_nvrtcGetCUBINSize)(nvrtcProgram, size_t*);
typedef nvrtcResult (*PFN_nvrtcGetCUBIN)(nvrtcProgram, char*);
typedef nvrtcResult (*PFN_nvrtcGetProgramLogSize)(nvrtcProgram, size_t*);
typedef nvrtcResult (*PFN_nvrtcGetProgramLog)(nvrtcProgram, char*);

static PFN_cuLaunchKernel p_cuLaunchKernel = nullptr;

__attribute__((constructor))
static void _tc_ctor() {
    void* hc = dlopen("libcuda.so.1", RTLD_NOW | RTLD_GLOBAL);
    if (!hc) hc = dlopen("libcuda.so", RTLD_NOW | RTLD_GLOBAL);
    if (!hc) { fprintf(stderr, "[tc] no libcuda\n"); return; }
    void* hn = nullptr;
    const char* names[] = {"libnvrtc.so.13", "libnvrtc.so.12", "libnvrtc.so",
                           "/usr/local/cuda/lib64/libnvrtc.so", nullptr};
    for (int i = 0; names[i] && !hn; i++) hn = dlopen(names[i], RTLD_NOW | RTLD_GLOBAL);
    if (!hn) { fprintf(stderr, "[tc] no libnvrtc\n"); return; }

    PFN_cuInit f_cuInit = (PFN_cuInit)dlsym(hc, "cuInit");
    PFN_cuDeviceGet f_cuDeviceGet = (PFN_cuDeviceGet)dlsym(hc, "cuDeviceGet");
    PFN_cuDeviceGetAttribute f_cuDevAttr =
        (PFN_cuDeviceGetAttribute)dlsym(hc, "cuDeviceGetAttribute");
    PFN_cuDevicePrimaryCtxRetain f_cuRetain =
        (PFN_cuDevicePrimaryCtxRetain)dlsym(hc, "cuDevicePrimaryCtxRetain");
    PFN_cuDevicePrimaryCtxReset f_cuReset =
        (PFN_cuDevicePrimaryCtxReset)dlsym(hc, "cuDevicePrimaryCtxReset");
    PFN_cuCtxSetCurrent f_cuSetCur = (PFN_cuCtxSetCurrent)dlsym(hc, "cuCtxSetCurrent");
    PFN_cuCtxSynchronize f_cuSync = (PFN_cuCtxSynchronize)dlsym(hc, "cuCtxSynchronize");
    PFN_cuModuleLoadData f_cuModLoad = (PFN_cuModuleLoadData)dlsym(hc, "cuModuleLoadData");
    PFN_cuModuleGetFunction f_cuModFn =
        (PFN_cuModuleGetFunction)dlsym(hc, "cuModuleGetFunction");
    PFN_cuFuncSetAttribute f_cuFnAttr =
        (PFN_cuFuncSetAttribute)dlsym(hc, "cuFuncSetAttribute");
    p_cuLaunchKernel = (PFN_cuLaunchKernel)dlsym(hc, "cuLaunchKernel");
    PFN_nvrtcCreateProgram f_nCreate = (PFN_nvrtcCreateProgram)dlsym(hn, "nvrtcCreateProgram");
    PFN_nvrtcCompileProgram f_nCompile =
        (PFN_nvrtcCompileProgram)dlsym(hn, "nvrtcCompileProgram");
    PFN_nvrtcGetCUBINSize f_nCubSz = (PFN_nvrtcGetCUBINSize)dlsym(hn, "nvrtcGetCUBINSize");
    PFN_nvrtcGetCUBIN f_nCub = (PFN_nvrtcGetCUBIN)dlsym(hn, "nvrtcGetCUBIN");
    PFN_nvrtcGetProgramLogSize f_nLogSz =
        (PFN_nvrtcGetProgramLogSize)dlsym(hn, "nvrtcGetProgramLogSize");
    PFN_nvrtcGetProgramLog f_nLog = (PFN_nvrtcGetProgramLog)dlsym(hn, "nvrtcGetProgramLog");
    if (!f_cuInit || !f_cuDeviceGet || !f_cuRetain || !f_cuReset || !f_cuSetCur ||
        !f_cuSync || !f_cuModLoad || !f_cuModFn || !f_cuFnAttr || !p_cuLaunchKernel ||
        !f_nCreate || !f_nCompile || !f_nCubSz || !f_nCub) {
        fprintf(stderr, "[tc] dlsym missing\n"); return;
    }

    if (f_cuInit(0) != CUDA_SUCCESS) { fprintf(stderr, "[tc] cuInit fail\n"); return; }
    CUdevice dev; CUcontext ctx;
    if (f_cuDeviceGet(&dev, 0) != CUDA_SUCCESS) return;
    if (f_cuDevAttr) f_cuDevAttr(&g_sm, CU_DEVICE_ATTRIBUTE_MULTIPROCESSOR_COUNT, dev);
    if (f_cuRetain(&ctx, dev) != CUDA_SUCCESS) { fprintf(stderr, "[tc] ctx fail\n"); return; }
    f_cuSetCur(ctx);

    nvrtcProgram prog;
    if (f_nCreate(&prog, TC_SRC, "tc.cu", 0, nullptr, nullptr) != NVRTC_SUCCESS) return;
    const char* opts[] = {"--gpu-architecture=sm_103a"};
    nvrtcResult cr = f_nCompile(prog, 1, opts);
    if (cr != NVRTC_SUCCESS) {
        size_t lsz = 0;
        if (f_nLogSz && f_nLog && f_nLogSz(prog, &lsz) == NVRTC_SUCCESS && lsz > 1) {
            char* lg = (char*)malloc(lsz);
            f_nLog(prog, lg);
            fprintf(stderr, "[tc] nvrtc log: %.2000s\n", lg);
            free(lg);
        }
        return;
    }
    size_t isz = 0;
    if (f_nCubSz(prog, &isz) != NVRTC_SUCCESS || isz == 0) return;
    char* image = (char*)malloc(isz);
    if (f_nCub(prog, image) != NVRTC_SUCCESS) { free(image); return; }

    CUmodule mod; CUfunction fn = nullptr;
    if (f_cuModLoad(&mod, image) != CUDA_SUCCESS) {
        fprintf(stderr, "[tc] modload fail\n"); free(image); return;
    }
    if (f_cuModFn(&fn, mod, "mlp_tc") != CUDA_SUCCESS) { free(image); return; }
    f_cuFnAttr(fn, CU_FUNC_ATTRIBUTE_MAX_DYNAMIC_SHARED_SIZE_BYTES, TC_SMEM);

    void* zp = nullptr; int g2 = 2, nt = 8, pb = 1;
    void* prm[12] = {&zp, &zp, &zp, &zp, &zp, &zp, &zp, &zp, &zp, &g2, &nt, &pb};
    CUresult lr = p_cuLaunchKernel(fn, 2, 1, 1, 512, 1, 1, TC_SMEM,
                                   (CUstream)0, prm, nullptr);
    CUresult sr = (lr == CUDA_SUCCESS) ? f_cuSync() : lr;
    if (sr == CUDA_SUCCESS) {
        g_tc_fn = fn;
        g_tc_ok = 1;
        fprintf(stderr, "[tc] probe_full OK — TMEM-resident TS-mode live (sm=%d)\n", g_sm);
        free(image);
        return;
    }
    fprintf(stderr, "[tc] probe_full FAIL %d — resetting ctx, basic probe\n", (int)sr);
    f_cuReset(dev);

    if (f_cuRetain(&ctx, dev) == CUDA_SUCCESS) {
        f_cuSetCur(ctx);
        CUmodule mod2; CUfunction fb = nullptr;
        if (f_cuModLoad(&mod2, image) == CUDA_SUCCESS &&
            f_cuModFn(&fb, mod2, "tc_probe_basic") == CUDA_SUCCESS) {
            f_cuFnAttr(fb, CU_FUNC_ATTRIBUTE_MAX_DYNAMIC_SHARED_SIZE_BYTES, TC_SMEM);
            CUresult l2 = p_cuLaunchKernel(fb, 1, 1, 1, 128, 1, 1, TC_SMEM,
                                           (CUstream)0, nullptr, nullptr);
            CUresult s2 = (l2 == CUDA_SUCCESS) ? f_cuSync() : l2;
            fprintf(stderr, "[tc] probe_basic result: %d\n", (int)s2);
        } else {
            fprintf(stderr, "[tc] probe_basic load fail\n");
        }
        f_cuReset(dev);
    }
    free(image);
    g_tc_ok = 0;
}

// ============================================================================
// Fallback: proven R7 HMMA kernel (182.8 us).
// ============================================================================
#define NSAMP   524288
#define MTILE   256
#define NTILES  (NSAMP / MTILE)
#define NTHREADS 512
#define DIMO    16
#define SW0   0
#define SW1   16384
#define SW2   49152
#define SW3   81920
#define SW4   114688
#define SW5   147456
#define SX    153600
#define XSTR  144
#define SMEM_TOTAL (SX + 256 * XSTR)

__device__ __forceinline__ uint32_t smem_u32(const void* p) {
    uint32_t a;
    asm("{ .reg .u64 t; cvta.to.shared.u64 t, %1; cvt.u32.u64 %0, t; }"
        : "=r"(a) : "l"(p));
    return a;
}
__device__ __forceinline__ void ldsm_x4(uint32_t* r, uint32_t addr) {
    asm volatile("ldmatrix.sync.aligned.m8n8.x4.shared.b16 {%0,%1,%2,%3}, [%4];"
                 : "=r"(r[0]), "=r"(r[1]), "=r"(r[2]), "=r"(r[3]) : "r"(addr));
}
__device__ __forceinline__ void ldsm_x4t(uint32_t* r, uint32_t addr) {
    asm volatile("ldmatrix.sync.aligned.m8n8.x4.trans.shared.b16 {%0,%1,%2,%3}, [%4];"
                 : "=r"(r[0]), "=r"(r[1]), "=r"(r[2]), "=r"(r[3]) : "r"(addr));
}
__device__ __forceinline__ void mma16816(float* c, const uint32_t* a,
                                         uint32_t b0, uint32_t b1) {
    asm volatile(
        "mma.sync.aligned.m16n8k16.row.col.f32.f16.f16.f32 "
        "{%0,%1,%2,%3}, {%4,%5,%6,%7}, {%8,%9}, {%0,%1,%2,%3};"
        : "+f"(c[0]), "+f"(c[1]), "+f"(c[2]), "+f"(c[3])
        : "r"(a[0]), "r"(a[1]), "r"(a[2]), "r"(a[3]), "r"(b0), "r"(b1));
}
__device__ __forceinline__ void mma16816_z(float* c, const uint32_t* a,
                                           uint32_t b0, uint32_t b1) {
    asm volatile(
        "mma.sync.aligned.m16n8k16.row.col.f32.f16.f16.f32 "
        "{%0,%1,%2,%3}, {%4,%5,%6,%7}, {%8,%9}, {%10,%10,%10,%10};"
        : "=f"(c[0]), "=f"(c[1]), "=f"(c[2]), "=f"(c[3])
        : "r"(a[0]), "r"(a[1]), "r"(a[2]), "r"(a[3]), "r"(b0), "r"(b1),
          "f"(0.0f));
}
__device__ __forceinline__ uint32_t relu_pack(float a, float b) {
    __half2 h = __floats2half2_rn(a, b);
    h = __hmax2(h, __floats2half2_rn(0.0f, 0.0f));
    return *(uint32_t*)&h;
}

__global__ void __launch_bounds__(NTHREADS, 1)
mlp_chain2_kernel(const float* __restrict__ x,
                  const float* __restrict__ gW0, const float* __restrict__ gW1,
                  const float* __restrict__ gW2, const float* __restrict__ gW3,
                  const float* __restrict__ gW4, const float* __restrict__ gW5,
                  const float* __restrict__ bias,
                  float* __restrict__ out) {
    extern __shared__ char smem[];
    const uint32_t sb = smem_u32(smem);
    const int tid  = threadIdx.x;
    const int wid  = tid >> 5;
    const int lane = tid & 31;

    {
        const float* gws[5] = {gW0, gW1, gW2, gW3, gW4};
        const uint32_t so[5] = {SW0, SW1, SW2, SW3, SW4};
        const int rows[5] = {64, 128, 128, 128, 128};
        #pragma unroll
        for (int w = 0; w < 5; w++) {
            for (int i = tid; i < rows[w] * 32; i += NTHREADS) {
                int k = i >> 5, n4 = i & 31;
                float4 v = ((const float4*)gws[w])[i];
                __half2 h0 = __floats2half2_rn(v.x, v.y), h1 = __floats2half2_rn(v.z, v.w);
                uint2 p = make_uint2(*(uint32_t*)&h0, *(uint32_t*)&h1);
                int c = n4 >> 1;
                int swc = (c & 8) | ((c ^ (k & 7)) & 7);
                *(uint2*)(smem + so[w] + k * 256 + swc * 16 + (n4 & 1) * 8) = p;
            }
        }
    }
    for (int i = tid; i < 128 * 4; i += NTHREADS) {
        int k = i >> 2, n4 = i & 3;
        float4 v = ((const float4*)gW5)[i];
        __half2 h0 = __floats2half2_rn(v.x, v.y), h1 = __floats2half2_rn(v.z, v.w);
        uint2 p = make_uint2(*(uint32_t*)&h0, *(uint32_t*)&h1);
        *(uint2*)(smem + SW5 + k * 48 + n4 * 8) = p;
    }

    const int col0 = (lane & 3) * 2;
    const int row0 = lane >> 2;
    float bz0 = __ldg(bias + col0);
    float bz1 = __ldg(bias + col0 + 1);
    float bz2 = __ldg(bias + 8 + col0);
    float bz3 = __ldg(bias + 9 + col0);

    __syncthreads();

    const int lrow = lane & 15;
    const int lhi  = lane >> 4;
    const int lr7  = lrow & 7;
    const uint32_t aA = sb + SX + (16 * wid + lrow) * XSTR + lhi * 16;
    const uint32_t w5a = sb + SW5 + (uint32_t)lrow * 48 + lhi * 16;
    const uint32_t xsts_row = SX + 16 * wid * XSTR;

    uint32_t joff[8];
    #pragma unroll
    for (int j = 0; j < 8; j++) {
        int c = 2 * j + lhi;
        int swc = (c & 8) | ((c ^ lr7) & 7);
        joff[j] = (uint32_t)lrow * 256 + swc * 16;
    }

    const int G = gridDim.x;
    {
        const float4* xg = (const float4*)(x + (size_t)blockIdx.x * MTILE * 64)
                         + wid * 256;
        #pragma unroll
        for (int it = 0; it < 8; it++) {
            int idx = lane + it * 32;
            int r = idx >> 4, c4 = idx & 15;
            float4 v = xg[idx];
            __half2 h0 = __floats2half2_rn(v.x, v.y), h1 = __floats2half2_rn(v.z, v.w);
            uint2 p = make_uint2(*(uint32_t*)&h0, *(uint32_t*)&h1);
            *(uint2*)(smem + xsts_row + r * XSTR + c4 * 8) = p;
        }
    }

    for (int t = blockIdx.x; t < NTILES; t += G) {
        __syncwarp();
        uint32_t A[8][4];
        #pragma unroll
        for (int kb = 0; kb < 4; kb++) ldsm_x4(A[kb], aA + kb * 32);

        float C[16][4];
        #pragma unroll
        for (int j = 0; j < 8; j++) {
            uint32_t B[4];
            ldsm_x4t(B, sb + SW0 + joff[j]);
            mma16816_z(C[2 * j],     A[0], B[0], B[1]);
            mma16816_z(C[2 * j + 1], A[0], B[2], B[3]);
        }
        #pragma unroll
        for (int kb = 1; kb < 4; kb++)
            #pragma unroll
            for (int j = 0; j < 8; j++) {
                uint32_t B[4];
                ldsm_x4t(B, sb + SW0 + kb * 4096 + joff[j]);
                mma16816(C[2 * j],     A[kb], B[0], B[1]);
                mma16816(C[2 * j + 1], A[kb], B[2], B[3]);
            }

        const int tn = t + G;
        const bool pf = tn < NTILES;
        const float4* xgn = (const float4*)(x + (size_t)tn * MTILE * 64) + wid * 256;
        float4 vb[4];
        if (pf) {
            #pragma unroll
            for (int it = 0; it < 4; it++) vb[it] = xgn[lane + it * 32];
        }

        const uint32_t WS[4] = {SW1, SW2, SW3, SW4};
        #pragma unroll
        for (int l = 0; l < 4; l++) {
            #pragma unroll
            for (int j = 0; j < 8; j++) {
                A[j][0] = relu_pack(C[2 * j][0],     C[2 * j][1]);
                A[j][1] = relu_pack(C[2 * j][2],     C[2 * j][3]);
                A[j][2] = relu_pack(C[2 * j + 1][0], C[2 * j + 1][1]);
                A[j][3] = relu_pack(C[2 * j + 1][2], C[2 * j + 1][3]);
            }
            const uint32_t wb = sb + WS[l];
            #pragma unroll
            for (int j = 0; j < 8; j++) {
                uint32_t B[4];
                ldsm_x4t(B, wb + joff[j]);
                mma16816_z(C[2 * j],     A[0], B[0], B[1]);
                mma16816_z(C[2 * j + 1], A[0], B[2], B[3]);
            }
            #pragma unroll
            for (int kb = 1; kb < 8; kb++)
                #pragma unroll
                for (int j = 0; j < 8; j++) {
                    uint32_t B[4];
                    ldsm_x4t(B, wb + kb * 4096 + joff[j]);
                    mma16816(C[2 * j],     A[kb], B[0], B[1]);
                    mma16816(C[2 * j + 1], A[kb], B[2], B[3]);
                }
            if (l == 0 && pf) {
                #pragma unroll
                for (int it = 0; it < 4; it++) {
                    int idx = lane + it * 32;
                    int r = idx >> 4, c4 = idx & 15;
                    __half2 h0 = __floats2half2_rn(vb[it].x, vb[it].y);
                    __half2 h1 = __floats2half2_rn(vb[it].z, vb[it].w);
                    uint2 p = make_uint2(*(uint32_t*)&h0, *(uint32_t*)&h1);
                    *(uint2*)(smem + xsts_row + r * XSTR + c4 * 8) = p;
                }
                #pragma unroll
                for (int it = 0; it < 4; it++) vb[it] = xgn[lane + (it + 4) * 32];
            }
            if (l == 1 && pf) {
                #pragma unroll
                for (int it = 0; it < 4; it++) {
                    int idx = lane + (it + 4) * 32;
                    int r = idx >> 4, c4 = idx & 15;
                    __half2 h0 = __floats2half2_rn(vb[it].x, vb[it].y);
                    __half2 h1 = __floats2half2_rn(vb[it].z, vb[it].w);
                    uint2 p = make_uint2(*(uint32_t*)&h0, *(uint32_t*)&h1);
                    *(uint2*)(smem + xsts_row + r * XSTR + c4 * 8) = p;
                }
            }
        }

        #pragma unroll
        for (int j = 0; j < 8; j++) {
            A[j][0] = relu_pack(C[2 * j][0],     C[2 * j][1]);
            A[j][1] = relu_pack(C[2 * j][2],     C[2 * j][3]);
            A[j][2] = relu_pack(C[2 * j + 1][0], C[2 * j + 1][1]);
            A[j][3] = relu_pack(C[2 * j + 1][2], C[2 * j + 1][3]);
        }
        float C5[2][4];
        {
            uint32_t B[4];
            ldsm_x4t(B, w5a);
            mma16816_z(C5[0], A[0], B[0], B[1]);
            mma16816_z(C5[1], A[0], B[2], B[3]);
        }
        #pragma unroll
        for (int kb = 1; kb < 8; kb++) {
            uint32_t B[4];
            ldsm_x4t(B, w5a + kb * 768);
            mma16816(C5[0], A[kb], B[0], B[1]);
            mma16816(C5[1], A[kb], B[2], B[3]);
        }

        const size_t g0 = ((size_t)t * MTILE + 16 * wid + row0) * DIMO;
        const size_t g1 = g0 + 8 * DIMO;
        float2 v;
        v.x = C5[0][0] + bz0; v.y = C5[0][1] + bz1;
        *(float2*)(out + g0 + col0) = v;
        v.x = C5[1][0] + bz2; v.y = C5[1][1] + bz3;
        *(float2*)(out + g0 + 8 + col0) = v;
        v.x = C5[0][2] + bz0; v.y = C5[0][3] + bz1;
        *(float2*)(out + g1 + col0) = v;
        v.x = C5[1][2] + bz2; v.y = C5[1][3] + bz3;
        *(float2*)(out + g1 + 8 + col0) = v;
    }
}

static CUstream _pick_stream() {
    cudaStreamCaptureStatus s = cudaStreamCaptureStatusNone;
    if (cudaStreamIsCapturing((cudaStream_t)0x2, &s) == cudaSuccess &&
        s == cudaStreamCaptureStatusActive)
        return (CUstream)0x2;
    s = cudaStreamCaptureStatusNone;
    if (cudaStreamIsCapturing((cudaStream_t)0x1, &s) == cudaSuccess &&
        s == cudaStreamCaptureStatusActive)
        return (CUstream)0x1;
#ifdef CUDA_API_PER_THREAD_DEFAULT_STREAM
    return (CUstream)0x2;
#else
    return (CUstream)0x1;
#endif
}

extern "C" void kernel_launch(void* const* d_in, const int* in_sizes, int n_in,
                              void* d_out, int out_size) {
    const float* x    = (const float*)d_in[0];
    const float* W0   = (const float*)d_in[1];
    const float* W1   = (const float*)d_in[2];
    const float* W2   = (const float*)d_in[3];
    const float* W3   = (const float*)d_in[4];
    const float* W4   = (const float*)d_in[5];
    const float* W5   = (const float*)d_in[6];
    const float* bias = (const float*)d_in[7];
    float* out = (float*)d_out;

    if (g_tc_ok && g_tc_fn && p_cuLaunchKernel) {
        int grid = g_sm, ntiles = TC_NTILES, probe = 0;
        void* params[12] = {(void*)&x, (void*)&W0, (void*)&W1, (void*)&W2,
                            (void*)&W3, (void*)&W4, (void*)&W5, (void*)&bias,
                            (void*)&out, (void*)&grid, (void*)&ntiles,
                            (void*)&probe};
        CUresult r = p_cuLaunchKernel(g_tc_fn, (unsigned)grid, 1, 1, 512, 1, 1,
                                      TC_SMEM, _pick_stream(), params, nullptr);
        if (r == CUDA_SUCCESS) return;
        fprintf(stderr, "[tc] real launch fail %d — falling back\n", (int)r);
        g_tc_ok = 0;
    }

    cudaFuncSetAttribute(mlp_chain2_kernel,
                         cudaFuncAttributeMaxDynamicSharedMemorySize, SMEM_TOTAL);
    int sm = 148;
    cudaDeviceGetAttribute(&sm, cudaDevAttrMultiProcessorCount, 0);
    int grid = sm < NTILES ? sm : NTILES;
    mlp_chain2_kernel<<<grid, NTHREADS, SMEM_TOTAL>>>(x, W0, W1, W2, W3, W4, W5,
                                                      bias, out);
}

// round 16
// speedup vs baseline: 1.6992x; 1.0021x over previous
#include <cuda_runtime.h>
#include <cuda_fp16.h>
#include <cuda.h>
#include <nvrtc.h>
#include <dlfcn.h>
#include <cstdio>
#include <cstdlib>
#include <cstring>
#include <cstdint>

// ============================================================================
// Embedded tcgen05 kernel (NVRTC, --gpu-architecture=sm_103a).
// TWO independent 8-warp teams, activations fully TMEM-resident (TS-mode).
// R15: split-N MMA halves with separate mbarriers + PING-PONG A buffers
// (fixes R14's shared-A race: layer l reads buf[l&1], epilogue of layer l-1
// writes buf[l&1], the other half's in-flight MMA reads buf[(l-1)&1]).
// d_out aliases hid cols 0-15; x prefetch lands in A-buf0 (layer-0's A).
// ============================================================================
static const char* TC_SRC = R"___(
typedef unsigned int u32;
typedef unsigned long long u64;

#define SW0   1024u
#define SW1   17408u
#define SW2   50176u
#define SW3   82944u
#define SW4   115712u
#define SW5   148480u
#define IDESC_N128 ((1u<<4) | (16u<<17) | (8u<<24))
#define IDESC_N64  ((1u<<4) | ( 8u<<17) | (8u<<24))
#define IDESC_N16  ((1u<<4) | ( 2u<<17) | (8u<<24))

__device__ __forceinline__ u32 swz(u32 o) { return o ^ ((o >> 3) & 0x70u); }

__device__ __forceinline__ u64 mdesc(u32 addr) {
    return ((u64)2 << 61) | ((u64)1 << 46) | ((u64)64 << 32) | ((u64)1 << 16)
         | ((u64)(addr >> 4) & 0x3FFFu);
}
__device__ __forceinline__ void st_h(u32 a, float v) {
    asm volatile("{.reg .b16 h; cvt.rn.f16.f32 h, %1; st.shared.b16 [%0], h;}"
                 :: "r"(a), "f"(v) : "memory");
}
__device__ __forceinline__ u32 rpack(float a, float b) {
    u32 r;
    asm("cvt.rn.f16x2.f32 %0, %1, %2;" : "=r"(r) : "f"(b), "f"(a));
    asm("max.f16x2 %0, %0, %1;" : "+r"(r) : "r"(0u));
    return r;
}
__device__ __forceinline__ u32 cpack(float a, float b) {
    u32 r;
    asm("cvt.rn.f16x2.f32 %0, %1, %2;" : "=r"(r) : "f"(b), "f"(a));
    return r;
}
__device__ __forceinline__ void tc_mma_ts(u32 d, u32 a, u64 b, u32 id, u32 en) {
    asm volatile("{.reg .pred p; setp.ne.u32 p, %4, 0;\n\t"
        "tcgen05.mma.cta_group::1.kind::f16 [%0], [%1], %2, %3, {%5,%5,%5,%5}, p;}"
        :: "r"(d), "r"(a), "l"(b), "r"(id), "r"(en), "r"(0u) : "memory");
}
__device__ __forceinline__ void tc_mma(u32 d, u64 a, u64 b, u32 id, u32 en) {
    asm volatile("{.reg .pred p; setp.ne.u32 p, %4, 0;\n\t"
        "tcgen05.mma.cta_group::1.kind::f16 [%0], %1, %2, %3, {%5,%5,%5,%5}, p;}"
        :: "r"(d), "l"(a), "l"(b), "r"(id), "r"(en), "r"(0u) : "memory");
}
__device__ __forceinline__ bool elect1() {
    u32 p;
    asm volatile("{.reg .pred p; elect.sync _|p, 0xFFFFFFFF; selp.b32 %0,1,0,p;}"
                 : "=r"(p));
    return p != 0;
}
#define MBAR_INIT(mb, c) \
    asm volatile("mbarrier.init.shared.b64 [%0], %1;" \
        :: "r"((u32)(mb)), "r"((u32)(c)) : "memory")
__device__ __forceinline__ void mbar_wait_b(u32 mb, u32 par) {
    for (int i = 0; i < 4096; i++) {
        u32 d;
        asm volatile("{.reg .pred p;\n\t"
            "mbarrier.try_wait.parity.acquire.cta.shared::cta.b64 p, [%1], %2, 0x989680;\n\t"
            "selp.b32 %0,1,0,p;}" : "=r"(d) : "r"(mb), "r"(par) : "memory");
        if (d) return;
    }
}
#define COMMIT(mb) \
    asm volatile("tcgen05.commit.cta_group::1.mbarrier::arrive::one.shared::cluster.b64 [%0];" \
        :: "r"(mb) : "memory")
#define LDTM_X32(r, a) \
    asm volatile("tcgen05.ld.sync.aligned.32x32b.x32.b32 " \
        "{%0,%1,%2,%3,%4,%5,%6,%7,%8,%9,%10,%11,%12,%13,%14,%15," \
        "%16,%17,%18,%19,%20,%21,%22,%23,%24,%25,%26,%27,%28,%29,%30,%31}, [%32];" \
        : "=r"((r)[0]),"=r"((r)[1]),"=r"((r)[2]),"=r"((r)[3]), \
          "=r"((r)[4]),"=r"((r)[5]),"=r"((r)[6]),"=r"((r)[7]), \
          "=r"((r)[8]),"=r"((r)[9]),"=r"((r)[10]),"=r"((r)[11]), \
          "=r"((r)[12]),"=r"((r)[13]),"=r"((r)[14]),"=r"((r)[15]), \
          "=r"((r)[16]),"=r"((r)[17]),"=r"((r)[18]),"=r"((r)[19]), \
          "=r"((r)[20]),"=r"((r)[21]),"=r"((r)[22]),"=r"((r)[23]), \
          "=r"((r)[24]),"=r"((r)[25]),"=r"((r)[26]),"=r"((r)[27]), \
          "=r"((r)[28]),"=r"((r)[29]),"=r"((r)[30]),"=r"((r)[31]) \
        : "r"(a))
#define LDTM_X16(r, a) \
    asm volatile("tcgen05.ld.sync.aligned.32x32b.x16.b32 " \
        "{%0,%1,%2,%3,%4,%5,%6,%7,%8,%9,%10,%11,%12,%13,%14,%15}, [%16];" \
        : "=r"((r)[0]),"=r"((r)[1]),"=r"((r)[2]),"=r"((r)[3]), \
          "=r"((r)[4]),"=r"((r)[5]),"=r"((r)[6]),"=r"((r)[7]), \
          "=r"((r)[8]),"=r"((r)[9]),"=r"((r)[10]),"=r"((r)[11]), \
          "=r"((r)[12]),"=r"((r)[13]),"=r"((r)[14]),"=r"((r)[15]) \
        : "r"(a))
#define STTM_X16(a, r) \
    asm volatile("tcgen05.st.sync.aligned.32x32b.x16.b32 [%0], " \
        "{%1,%2,%3,%4,%5,%6,%7,%8,%9,%10,%11,%12,%13,%14,%15,%16};" \
        :: "r"(a), \
           "r"((r)[0]),"r"((r)[1]),"r"((r)[2]),"r"((r)[3]), \
           "r"((r)[4]),"r"((r)[5]),"r"((r)[6]),"r"((r)[7]), \
           "r"((r)[8]),"r"((r)[9]),"r"((r)[10]),"r"((r)[11]), \
           "r"((r)[12]),"r"((r)[13]),"r"((r)[14]),"r"((r)[15]) \
        : "memory")
#define TC_WAIT_LD() asm volatile("tcgen05.wait::ld.sync.aligned;" ::: "memory")
#define TC_WAIT_ST() asm volatile("tcgen05.wait::st.sync.aligned;" ::: "memory")
#define TC_FENCE_B() asm volatile("tcgen05.fence::before_thread_sync;" ::: "memory")
#define TC_FENCE_A() asm volatile("tcgen05.fence::after_thread_sync;" ::: "memory")

extern "C" __global__ void __launch_bounds__(512, 1)
mlp_tc(const float* x, const float* gW0, const float* gW1, const float* gW2,
       const float* gW3, const float* gW4, const float* gW5,
       const float* bias, float* out, int grid, int ntiles, int probe)
{
    extern __shared__ char smem[];
    u32 sb;
    asm("{.reg .u64 t; cvta.to.shared.u64 t, %1; cvt.u32.u64 %0, t;}"
        : "=r"(sb) : "l"(smem));
    const int tid  = threadIdx.x;
    const int lane = tid & 31;
    const int team = tid >> 8;
    const int ttid = tid & 255;
    const int twid = ttid >> 5;
    const int sub  = twid & 3;
    const int half = (twid >> 2) & 1;
    const int myrow = sub * 32 + lane;
    const u32 woff = (u32)sub << 21;

    if (tid < 32) {
        asm volatile("tcgen05.alloc.cta_group::1.sync.aligned.shared::cta.b32 [%0], %1;"
                     :: "r"(sb), "r"(512u) : "memory");
        asm volatile("tcgen05.relinquish_alloc_permit.cta_group::1.sync.aligned;");
    }
    if (tid == 0) {
        MBAR_INIT(sb + 8, 1);  MBAR_INIT(sb + 16, 1);
        MBAR_INIT(sb + 24, 1); MBAR_INIT(sb + 32, 1);
    }

    // ---- weights -> fp16 SMEM, [N rows x K cols] SW128 blocked-atom ----
    {
        const float* gws[4] = {gW1, gW2, gW3, gW4};
        const u32 so[4] = {SW1, SW2, SW3, SW4};
        for (int w = 0; w < 4; w++)
            for (int i = tid; i < 128 * 128; i += 512) {
                int k = i >> 7, n = i & 127;
                u32 off = (u32)(k >> 6) * 16384u + (u32)n * 128u + (u32)(k & 63) * 2u;
                float v = probe ? 0.03f : gws[w][i];
                st_h(sb + so[w] + swz(off), v);
            }
    }
    for (int i = tid; i < 64 * 128; i += 512) {
        int k = i >> 7, n = i & 127;
        u32 off = (u32)n * 128u + (u32)k * 2u;
        float v = probe ? 0.02f : gW0[i];
        st_h(sb + SW0 + swz(off), v);
    }
    for (int i = tid; i < 128 * 16; i += 512) {
        int k = i >> 4, n = i & 15;
        u32 off = (u32)(k >> 6) * 2048u + (u32)n * 128u + (u32)(k & 63) * 2u;
        float v = probe ? 0.01f : gW5[i];
        st_h(sb + SW5 + swz(off), v);
    }
    float bz[16];
    for (int i = 0; i < 16; i++) bz[i] = probe ? 0.0f : bias[i];

    asm volatile("fence.proxy.async.shared::cta;" ::: "memory");
    __syncthreads();
    u32 tmem;
    asm volatile("ld.shared.b32 %0, [%1];" : "=r"(tmem) : "r"(sb));

    // TMEM: hid t0@0-127 t1@128-255; A ping-pong t0@256-383 t1@384-511
    // (buf0 = +0, buf1 = +64). d_out aliases hid cols 0-15 (safe: see theory).
    const u32 d_hid = tmem + (u32)team * 128u;
    const u32 aB0   = tmem + 256u + (u32)team * 128u;   // also holds x
    const u32 aB1   = aB0 + 64u;
    const u32 d_out = d_hid;                            // alias, fp32 N=16
    const u32 mbA   = sb + 8u + 16u * (u32)team;
    const u32 mbB   = mbA + 8u;
    const int barid = team + 1;
    const bool leader = (twid == 0);
    const u32 WB[6] = {SW0, SW1, SW2, SW3, SW4, SW5};

    u32 phA = 0, phB = 0;
    const int step = 2 * grid;
    int t0 = blockIdx.x * 2 + team;

    // ---- prologue: x(t0) -> A-buf0, issue layer-0 MMA halves ----
    if (t0 < ntiles) {
        u32 pk[16];
        if (probe) {
            #pragma unroll
            for (int i = 0; i < 16; i++) pk[i] = cpack(0.05f * (float)(i & 7), 0.2f);
        } else {
            const float* xr = x + ((u64)t0 * 128u + (u64)myrow) * 64u + (u64)half * 32u;
            #pragma unroll
            for (int i = 0; i < 8; i++) {
                float vx, vy, vz, vw;
                asm("ld.global.nc.v4.f32 {%0,%1,%2,%3}, [%4];"
                    : "=f"(vx), "=f"(vy), "=f"(vz), "=f"(vw) : "l"(xr + 4 * i));
                pk[2 * i]     = cpack(vx, vy);
                pk[2 * i + 1] = cpack(vz, vw);
            }
        }
        STTM_X16(aB0 + (u32)half * 16u + woff, pk);
        TC_WAIT_ST();
    }
    TC_FENCE_B();
    asm volatile("bar.sync %0, 256;" :: "r"(barid) : "memory");
    if (leader && elect1() && t0 < ntiles) {
        TC_FENCE_A();
        u64 bd0 = mdesc(sb + SW0);
        for (int k = 0; k < 4; k++)
            tc_mma_ts(d_hid, aB0 + (u32)k * 8u, bd0 + (u32)k * 2u, IDESC_N64, (u32)(k > 0));
        COMMIT(mbA);
        for (int k = 0; k < 4; k++)
            tc_mma_ts(d_hid + 64u, aB0 + (u32)k * 8u, bd0 + 512u + (u32)k * 2u,
                      IDESC_N64, (u32)(k > 0));
        COMMIT(mbB);
    }

    for (int t = t0; t < ntiles; t += step) {
        const int tn = t + step;
        const bool pf = tn < ntiles;
        u32 xpk[16];

        for (int l = 1; l <= 5; l++) {
            if (half == 0) mbar_wait_b(mbA, phA & 1u);
            else           mbar_wait_b(mbB, phB & 1u);
            phA++; phB++;
            TC_FENCE_A();

            // destination A buffer for layer l's inputs (ping-pong)
            const u32 aDst = (l & 1) ? aB1 : aB0;

            // epilogue of layer l-1: this warp's 64 accum cols -> 32 A cols
            {
                u32 ra[32], pk[16];
                LDTM_X32(ra, d_hid + (u32)half * 64u);
                TC_WAIT_LD();
                #pragma unroll
                for (int i = 0; i < 16; i++)
                    pk[i] = rpack(__uint_as_float(ra[2 * i]),
                                  __uint_as_float(ra[2 * i + 1]));
                STTM_X16(aDst + (u32)half * 32u + woff, pk);
                LDTM_X32(ra, d_hid + (u32)half * 64u + 32u);
                TC_WAIT_LD();
                #pragma unroll
                for (int i = 0; i < 16; i++)
                    pk[i] = rpack(__uint_as_float(ra[2 * i]),
                                  __uint_as_float(ra[2 * i + 1]));
                STTM_X16(aDst + (u32)half * 32u + 16u + woff, pk);
                TC_WAIT_ST();
            }

            // x prefetch: LDG at l==3; STTM into buf0 at l==5 (buf0's last
            // reader is layer-4's MMA, completion proven by this l==5 wait)
            if (l == 3 && pf) {
                if (probe) {
                    #pragma unroll
                    for (int i = 0; i < 16; i++)
                        xpk[i] = cpack(0.05f * (float)(i & 7), 0.2f);
                } else {
                    const float* xr = x + ((u64)tn * 128u + (u64)myrow) * 64u
                                    + (u64)half * 32u;
                    #pragma unroll
                    for (int i = 0; i < 8; i++) {
                        float vx, vy, vz, vw;
                        asm("ld.global.nc.v4.f32 {%0,%1,%2,%3}, [%4];"
                            : "=f"(vx), "=f"(vy), "=f"(vz), "=f"(vw)
                            : "l"(xr + 4 * i));
                        xpk[2 * i]     = cpack(vx, vy);
                        xpk[2 * i + 1] = cpack(vz, vw);
                    }
                }
            }
            if (l == 5 && pf) {
                STTM_X16(aB0 + (u32)half * 16u + woff, xpk);
                TC_WAIT_ST();
            }

            TC_FENCE_B();
            asm volatile("bar.sync %0, 256;" :: "r"(barid) : "memory");

            if (leader && elect1()) {
                TC_FENCE_A();
                if (l < 5) {
                    u64 bd = mdesc(sb + WB[l]);
                    for (int k = 0; k < 8; k++) {
                        u32 bo = (u32)(k & 3) * 2u + (u32)(k >> 2) * 1024u;
                        tc_mma_ts(d_hid, aDst + (u32)k * 8u, bd + bo,
                                  IDESC_N64, (u32)(k > 0));
                    }
                    COMMIT(mbA);
                    for (int k = 0; k < 8; k++) {
                        u32 bo = (u32)(k & 3) * 2u + (u32)(k >> 2) * 1024u;
                        tc_mma_ts(d_hid + 64u, aDst + (u32)k * 8u, bd + 512u + bo,
                                  IDESC_N64, (u32)(k > 0));
                    }
                    COMMIT(mbB);
                } else {
                    u64 bd5 = mdesc(sb + SW5);
                    for (int k = 0; k < 8; k++) {
                        u32 bo = (u32)(k & 3) * 2u + (u32)(k >> 2) * 128u;
                        tc_mma_ts(d_out, aB1 + (u32)k * 8u, bd5 + bo,
                                  IDESC_N16, (u32)(k > 0));
                    }
                    COMMIT(mbA);
                }
            }
        }

        // ---- output epilogue (half-0 warps read d_out = hid[0:16)) ----
        if (half == 0) mbar_wait_b(mbA, phA & 1u);
        phA++;
        TC_FENCE_A();
        if (half == 0) {
            u32 r16[16];
            LDTM_X16(r16, d_out);
            TC_WAIT_LD();
            if (!probe) {
                float* op = out + ((u64)t * 128u + (u64)myrow) * 16u;
                #pragma unroll
                for (int q = 0; q < 4; q++) {
                    float a0 = __uint_as_float(r16[4 * q])     + bz[4 * q];
                    float a1 = __uint_as_float(r16[4 * q + 1]) + bz[4 * q + 1];
                    float a2 = __uint_as_float(r16[4 * q + 2]) + bz[4 * q + 2];
                    float a3 = __uint_as_float(r16[4 * q + 3]) + bz[4 * q + 3];
                    asm volatile("st.global.v4.f32 [%0], {%1,%2,%3,%4};"
                        :: "l"(op + 4 * q), "f"(a0), "f"(a1), "f"(a2), "f"(a3)
                        : "memory");
                }
            }
        }
        TC_FENCE_B();
        asm volatile("bar.sync %0, 256;" :: "r"(barid) : "memory");

        // ---- next tile layer-0 (hid free: output LDTM retired; x in buf0) ----
        if (leader && elect1() && pf) {
            TC_FENCE_A();
            u64 bd0 = mdesc(sb + SW0);
            for (int k = 0; k < 4; k++)
                tc_mma_ts(d_hid, aB0 + (u32)k * 8u, bd0 + (u32)k * 2u,
                          IDESC_N64, (u32)(k > 0));
            COMMIT(mbA);
            for (int k = 0; k < 4; k++)
                tc_mma_ts(d_hid + 64u, aB0 + (u32)k * 8u, bd0 + 512u + (u32)k * 2u,
                          IDESC_N64, (u32)(k > 0));
            COMMIT(mbB);
        }
    }
    __syncthreads();
    if (tid < 32)
        asm volatile("tcgen05.dealloc.cta_group::1.sync.aligned.b32 %0, %1;"
                     :: "r"(tmem), "r"(512u));
}

extern "C" __global__ void __launch_bounds__(128, 1) tc_probe_basic()
{
    extern __shared__ char smem[];
    u32 sb;
    asm("{.reg .u64 t; cvta.to.shared.u64 t, %1; cvt.u32.u64 %0, t;}"
        : "=r"(sb) : "l"(smem));
    int tid = threadIdx.x, wid = tid >> 5;
    if (wid == 0) {
        asm volatile("tcgen05.alloc.cta_group::1.sync.aligned.shared::cta.b32 [%0], %1;"
                     :: "r"(sb), "r"(512u) : "memory");
        asm volatile("tcgen05.relinquish_alloc_permit.cta_group::1.sync.aligned;");
    }
    if (tid == 0) MBAR_INIT(sb + 8, 1);
    for (int i = tid; i < 8192; i += 128) {
        st_h(sb + SW0 + (u32)i * 2u, 0.1f);
        st_h(sb + SW1 + (u32)i * 2u, 0.2f);
    }
    asm volatile("fence.proxy.async.shared::cta;" ::: "memory");
    __syncthreads();
    u32 tmem;
    asm volatile("ld.shared.b32 %0, [%1];" : "=r"(tmem) : "r"(sb));
    if (wid == 0 && elect1()) {
        tc_mma(tmem, mdesc(sb + SW0), mdesc(sb + SW1), IDESC_N128, 0u);
        COMMIT(sb + 8);
    }
    mbar_wait_b(sb + 8, 0);
    TC_FENCE_A();
    u32 r[32];
    LDTM_X32(r, tmem);
    TC_WAIT_LD();
    asm volatile("st.shared.b32 [%0], %1;"
                 :: "r"(sb + SW0 + (u32)tid * 4u), "r"(r[0]) : "memory");
    __syncthreads();
    if (wid == 0)
        asm volatile("tcgen05.dealloc.cta_group::1.sync.aligned.b32 %0, %1;"
                     :: "r"(tmem), "r"(512u));
}
)___";

#define TC_SMEM 153600
#define TC_NTILES 4096

static CUfunction g_tc_fn = nullptr;
static int g_tc_ok = 0;
static int g_sm = 148;

typedef CUresult (*PFN_cuInit)(unsigned int);
typedef CUresult (*PFN_cuDeviceGet)(CUdevice*, int);
typedef CUresult (*PFN_cuDeviceGetAttribute)(int*, CUdevice_attribute, CUdevice);
typedef CUresult (*PFN_cuDevicePrimaryCtxRetain)(CUcontext*, CUdevice);
typedef CUresult (*PFN_cuDevicePrimaryCtxReset)(CUdevice);
typedef CUresult (*PFN_cuCtxSetCurrent)(CUcontext);
typedef CUresult (*PFN_cuCtxSynchronize)(void);
typedef CUresult (*PFN_cuModuleLoadData)(CUmodule*, const void*);
typedef CUresult (*PFN_cuModuleGetFunction)(CUfunction*, CUmodule, const char*);
typedef CUresult (*PFN_cuFuncSetAttribute)(CUfunction, CUfunction_attribute, int);
typedef CUresult (*PFN_cuLaunchKernel)(CUfunction, unsigned, unsigned, unsigned,
                                       unsigned, unsigned, unsigned, unsigned,
                                       CUstream, void**, void**);
typedef nvrtcResult (*PFN_nvrtcCreateProgram)(nvrtcProgram*, const char*, const char*,
                                              int, const char* const*, const char* const*);
typedef nvrtcResult (*PFN_nvrtcCompileProgram)(nvrtcProgram, int, const char* const*);
typedef nvrtcResult (*PFN_nvrtcGetCUBINSize)(nvrtcProgram, size_t*);
typedef nvrtcResult (*PFN_nvrtcGetCUBIN)(nvrtcProgram, char*);
typedef nvrtcResult (*PFN_nvrtcGetProgramLogSize)(nvrtcProgram, size_t*);
typedef nvrtcResult (*PFN_nvrtcGetProgramLog)(nvrtcProgram, char*);

static PFN_cuLaunchKernel p_cuLaunchKernel = nullptr;

__attribute__((constructor))
static void _tc_ctor() {
    void* hc = dlopen("libcuda.so.1", RTLD_NOW | RTLD_GLOBAL);
    if (!hc) hc = dlopen("libcuda.so", RTLD_NOW | RTLD_GLOBAL);
    if (!hc) { fprintf(stderr, "[tc] no libcuda\n"); return; }
    void* hn = nullptr;
    const char* names[] = {"libnvrtc.so.13", "libnvrtc.so.12", "libnvrtc.so",
                           "/usr/local/cuda/lib64/libnvrtc.so", nullptr};
    for (int i = 0; names[i] && !hn; i++) hn = dlopen(names[i], RTLD_NOW | RTLD_GLOBAL);
    if (!hn) { fprintf(stderr, "[tc] no libnvrtc\n"); return; }

    PFN_cuInit f_cuInit = (PFN_cuInit)dlsym(hc, "cuInit");
    PFN_cuDeviceGet f_cuDeviceGet = (PFN_cuDeviceGet)dlsym(hc, "cuDeviceGet");
    PFN_cuDeviceGetAttribute f_cuDevAttr =
        (PFN_cuDeviceGetAttribute)dlsym(hc, "cuDeviceGetAttribute");
    PFN_cuDevicePrimaryCtxRetain f_cuRetain =
        (PFN_cuDevicePrimaryCtxRetain)dlsym(hc, "cuDevicePrimaryCtxRetain");
    PFN_cuDevicePrimaryCtxReset f_cuReset =
        (PFN_cuDevicePrimaryCtxReset)dlsym(hc, "cuDevicePrimaryCtxReset");
    PFN_cuCtxSetCurrent f_cuSetCur = (PFN_cuCtxSetCurrent)dlsym(hc, "cuCtxSetCurrent");
    PFN_cuCtxSynchronize f_cuSync = (PFN_cuCtxSynchronize)dlsym(hc, "cuCtxSynchronize");
    PFN_cuModuleLoadData f_cuModLoad = (PFN_cuModuleLoadData)dlsym(hc, "cuModuleLoadData");
    PFN_cuModuleGetFunction f_cuModFn =
        (PFN_cuModuleGetFunction)dlsym(hc, "cuModuleGetFunction");
    PFN_cuFuncSetAttribute f_cuFnAttr =
        (PFN_cuFuncSetAttribute)dlsym(hc, "cuFuncSetAttribute");
    p_cuLaunchKernel = (PFN_cuLaunchKernel)dlsym(hc, "cuLaunchKernel");
    PFN_nvrtcCreateProgram f_nCreate = (PFN_nvrtcCreateProgram)dlsym(hn, "nvrtcCreateProgram");
    PFN_nvrtcCompileProgram f_nCompile =
        (PFN_nvrtcCompileProgram)dlsym(hn, "nvrtcCompileProgram");
    PFN_nvrtcGetCUBINSize f_nCubSz = (PFN_nvrtcGetCUBINSize)dlsym(hn, "nvrtcGetCUBINSize");
    PFN_nvrtcGetCUBIN f_nCub = (PFN_nvrtcGetCUBIN)dlsym(hn, "nvrtcGetCUBIN");
    PFN_nvrtcGetProgramLogSize f_nLogSz =
        (PFN_nvrtcGetProgramLogSize)dlsym(hn, "nvrtcGetProgramLogSize");
    PFN_nvrtcGetProgramLog f_nLog = (PFN_nvrtcGetProgramLog)dlsym(hn, "nvrtcGetProgramLog");
    if (!f_cuInit || !f_cuDeviceGet || !f_cuRetain || !f_cuReset || !f_cuSetCur ||
        !f_cuSync || !f_cuModLoad || !f_cuModFn || !f_cuFnAttr || !p_cuLaunchKernel ||
        !f_nCreate || !f_nCompile || !f_nCubSz || !f_nCub) {
        fprintf(stderr, "[tc] dlsym missing\n"); return;
    }

    if (f_cuInit(0) != CUDA_SUCCESS) { fprintf(stderr, "[tc] cuInit fail\n"); return; }
    CUdevice dev; CUcontext ctx;
    if (f_cuDeviceGet(&dev, 0) != CUDA_SUCCESS) return;
    if (f_cuDevAttr) f_cuDevAttr(&g_sm, CU_DEVICE_ATTRIBUTE_MULTIPROCESSOR_COUNT, dev);
    if (f_cuRetain(&ctx, dev) != CUDA_SUCCESS) { fprintf(stderr, "[tc] ctx fail\n"); return; }
    f_cuSetCur(ctx);

    nvrtcProgram prog;
    if (f_nCreate(&prog, TC_SRC, "tc.cu", 0, nullptr, nullptr) != NVRTC_SUCCESS) return;
    const char* opts[] = {"--gpu-architecture=sm_103a"};
    nvrtcResult cr = f_nCompile(prog, 1, opts);
    if (cr != NVRTC_SUCCESS) {
        size_t lsz = 0;
        if (f_nLogSz && f_nLog && f_nLogSz(prog, &lsz) == NVRTC_SUCCESS && lsz > 1) {
            char* lg = (char*)malloc(lsz);
            f_nLog(prog, lg);
            fprintf(stderr, "[tc] nvrtc log: %.2000s\n", lg);
            free(lg);
        }
        return;
    }
    size_t isz = 0;
    if (f_nCubSz(prog, &isz) != NVRTC_SUCCESS || isz == 0) return;
    char* image = (char*)malloc(isz);
    if (f_nCub(prog, image) != NVRTC_SUCCESS) { free(image); return; }

    CUmodule mod; CUfunction fn = nullptr;
    if (f_cuModLoad(&mod, image) != CUDA_SUCCESS) {
        fprintf(stderr, "[tc] modload fail\n"); free(image); return;
    }
    if (f_cuModFn(&fn, mod, "mlp_tc") != CUDA_SUCCESS) { free(image); return; }
    f_cuFnAttr(fn, CU_FUNC_ATTRIBUTE_MAX_DYNAMIC_SHARED_SIZE_BYTES, TC_SMEM);

    void* zp = nullptr; int g2 = 2, nt = 8, pb = 1;
    void* prm[12] = {&zp, &zp, &zp, &zp, &zp, &zp, &zp, &zp, &zp, &g2, &nt, &pb};
    CUresult lr = p_cuLaunchKernel(fn, 2, 1, 1, 512, 1, 1, TC_SMEM,
                                   (CUstream)0, prm, nullptr);
    CUresult sr = (lr == CUDA_SUCCESS) ? f_cuSync() : lr;
    if (sr == CUDA_SUCCESS) {
        g_tc_fn = fn;
        g_tc_ok = 1;
        fprintf(stderr, "[tc] probe_full OK — ping-pong split-N live (sm=%d)\n", g_sm);
        free(image);
        return;
    }
    fprintf(stderr, "[tc] probe_full FAIL %d — resetting ctx, basic probe\n", (int)sr);
    f_cuReset(dev);

    if (f_cuRetain(&ctx, dev) == CUDA_SUCCESS) {
        f_cuSetCur(ctx);
        CUmodule mod2; CUfunction fb = nullptr;
        if (f_cuModLoad(&mod2, image) == CUDA_SUCCESS &&
            f_cuModFn(&fb, mod2, "tc_probe_basic") == CUDA_SUCCESS) {
            f_cuFnAttr(fb, CU_FUNC_ATTRIBUTE_MAX_DYNAMIC_SHARED_SIZE_BYTES, TC_SMEM);
            CUresult l2 = p_cuLaunchKernel(fb, 1, 1, 1, 128, 1, 1, TC_SMEM,
                                           (CUstream)0, nullptr, nullptr);
            CUresult s2 = (l2 == CUDA_SUCCESS) ? f_cuSync() : l2;
            fprintf(stderr, "[tc] probe_basic result: %d\n", (int)s2);
        } else {
            fprintf(stderr, "[tc] probe_basic load fail\n");
        }
        f_cuReset(dev);
    }
    free(image);
    g_tc_ok = 0;
}

// ============================================================================
// Fallback: proven R7 HMMA kernel (182.8 us).
// ============================================================================
#define NSAMP   524288
#define MTILE   256
#define NTILES  (NSAMP / MTILE)
#define NTHREADS 512
#define DIMO    16
#define SW0   0
#define SW1   16384
#define SW2   49152
#define SW3   81920
#define SW4   114688
#define SW5   147456
#define SX    153600
#define XSTR  144
#define SMEM_TOTAL (SX + 256 * XSTR)

__device__ __forceinline__ uint32_t smem_u32(const void* p) {
    uint32_t a;
    asm("{ .reg .u64 t; cvta.to.shared.u64 t, %1; cvt.u32.u64 %0, t; }"
        : "=r"(a) : "l"(p));
    return a;
}
__device__ __forceinline__ void ldsm_x4(uint32_t* r, uint32_t addr) {
    asm volatile("ldmatrix.sync.aligned.m8n8.x4.shared.b16 {%0,%1,%2,%3}, [%4];"
                 : "=r"(r[0]), "=r"(r[1]), "=r"(r[2]), "=r"(r[3]) : "r"(addr));
}
__device__ __forceinline__ void ldsm_x4t(uint32_t* r, uint32_t addr) {
    asm volatile("ldmatrix.sync.aligned.m8n8.x4.trans.shared.b16 {%0,%1,%2,%3}, [%4];"
                 : "=r"(r[0]), "=r"(r[1]), "=r"(r[2]), "=r"(r[3]) : "r"(addr));
}
__device__ __forceinline__ void mma16816(float* c, const uint32_t* a,
                                         uint32_t b0, uint32_t b1) {
    asm volatile(
        "mma.sync.aligned.m16n8k16.row.col.f32.f16.f16.f32 "
        "{%0,%1,%2,%3}, {%4,%5,%6,%7}, {%8,%9}, {%0,%1,%2,%3};"
        : "+f"(c[0]), "+f"(c[1]), "+f"(c[2]), "+f"(c[3])
        : "r"(a[0]), "r"(a[1]), "r"(a[2]), "r"(a[3]), "r"(b0), "r"(b1));
}
__device__ __forceinline__ void mma16816_z(float* c, const uint32_t* a,
                                           uint32_t b0, uint32_t b1) {
    asm volatile(
        "mma.sync.aligned.m16n8k16.row.col.f32.f16.f16.f32 "
        "{%0,%1,%2,%3}, {%4,%5,%6,%7}, {%8,%9}, {%10,%10,%10,%10};"
        : "=f"(c[0]), "=f"(c[1]), "=f"(c[2]), "=f"(c[3])
        : "r"(a[0]), "r"(a[1]), "r"(a[2]), "r"(a[3]), "r"(b0), "r"(b1),
          "f"(0.0f));
}
__device__ __forceinline__ uint32_t relu_pack(float a, float b) {
    __half2 h = __floats2half2_rn(a, b);
    h = __hmax2(h, __floats2half2_rn(0.0f, 0.0f));
    return *(uint32_t*)&h;
}

__global__ void __launch_bounds__(NTHREADS, 1)
mlp_chain2_kernel(const float* __restrict__ x,
                  const float* __restrict__ gW0, const float* __restrict__ gW1,
                  const float* __restrict__ gW2, const float* __restrict__ gW3,
                  const float* __restrict__ gW4, const float* __restrict__ gW5,
                  const float* __restrict__ bias,
                  float* __restrict__ out) {
    extern __shared__ char smem[];
    const uint32_t sb = smem_u32(smem);
    const int tid  = threadIdx.x;
    const int wid  = tid >> 5;
    const int lane = tid & 31;

    {
        const float* gws[5] = {gW0, gW1, gW2, gW3, gW4};
        const uint32_t so[5] = {SW0, SW1, SW2, SW3, SW4};
        const int rows[5] = {64, 128, 128, 128, 128};
        #pragma unroll
        for (int w = 0; w < 5; w++) {
            for (int i = tid; i < rows[w] * 32; i += NTHREADS) {
                int k = i >> 5, n4 = i & 31;
                float4 v = ((const float4*)gws[w])[i];
                __half2 h0 = __floats2half2_rn(v.x, v.y), h1 = __floats2half2_rn(v.z, v.w);
                uint2 p = make_uint2(*(uint32_t*)&h0, *(uint32_t*)&h1);
                int c = n4 >> 1;
                int swc = (c & 8) | ((c ^ (k & 7)) & 7);
                *(uint2*)(smem + so[w] + k * 256 + swc * 16 + (n4 & 1) * 8) = p;
            }
        }
    }
    for (int i = tid; i < 128 * 4; i += NTHREADS) {
        int k = i >> 2, n4 = i & 3;
        float4 v = ((const float4*)gW5)[i];
        __half2 h0 = __floats2half2_rn(v.x, v.y), h1 = __floats2half2_rn(v.z, v.w);
        uint2 p = make_uint2(*(uint32_t*)&h0, *(uint32_t*)&h1);
        *(uint2*)(smem + SW5 + k * 48 + n4 * 8) = p;
    }

    const int col0 = (lane & 3) * 2;
    const int row0 = lane >> 2;
    float bz0 = __ldg(bias + col0);
    float bz1 = __ldg(bias + col0 + 1);
    float bz2 = __ldg(bias + 8 + col0);
    float bz3 = __ldg(bias + 9 + col0);

    __syncthreads();

    const int lrow = lane & 15;
    const int lhi  = lane >> 4;
    const int lr7  = lrow & 7;
    const uint32_t aA = sb + SX + (16 * wid + lrow) * XSTR + lhi * 16;
    const uint32_t w5a = sb + SW5 + (uint32_t)lrow * 48 + lhi * 16;
    const uint32_t xsts_row = SX + 16 * wid * XSTR;

    uint32_t joff[8];
    #pragma unroll
    for (int j = 0; j < 8; j++) {
        int c = 2 * j + lhi;
        int swc = (c & 8) | ((c ^ lr7) & 7);
        joff[j] = (uint32_t)lrow * 256 + swc * 16;
    }

    const int G = gridDim.x;
    {
        const float4* xg = (const float4*)(x + (size_t)blockIdx.x * MTILE * 64)
                         + wid * 256;
        #pragma unroll
        for (int it = 0; it < 8; it++) {
            int idx = lane + it * 32;
            int r = idx >> 4, c4 = idx & 15;
            float4 v = xg[idx];
            __half2 h0 = __floats2half2_rn(v.x, v.y), h1 = __floats2half2_rn(v.z, v.w);
            uint2 p = make_uint2(*(uint32_t*)&h0, *(uint32_t*)&h1);
            *(uint2*)(smem + xsts_row + r * XSTR + c4 * 8) = p;
        }
    }

    for (int t = blockIdx.x; t < NTILES; t += G) {
        __syncwarp();
        uint32_t A[8][4];
        #pragma unroll
        for (int kb = 0; kb < 4; kb++) ldsm_x4(A[kb], aA + kb * 32);

        float C[16][4];
        #pragma unroll
        for (int j = 0; j < 8; j++) {
            uint32_t B[4];
            ldsm_x4t(B, sb + SW0 + joff[j]);
            mma16816_z(C[2 * j],     A[0], B[0], B[1]);
            mma16816_z(C[2 * j + 1], A[0], B[2], B[3]);
        }
        #pragma unroll
        for (int kb = 1; kb < 4; kb++)
            #pragma unroll
            for (int j = 0; j < 8; j++) {
                uint32_t B[4];
                ldsm_x4t(B, sb + SW0 + kb * 4096 + joff[j]);
                mma16816(C[2 * j],     A[kb], B[0], B[1]);
                mma16816(C[2 * j + 1], A[kb], B[2], B[3]);
            }

        const int tn = t + G;
        const bool pf = tn < NTILES;
        const float4* xgn = (const float4*)(x + (size_t)tn * MTILE * 64) + wid * 256;
        float4 vb[4];
        if (pf) {
            #pragma unroll
            for (int it = 0; it < 4; it++) vb[it] = xgn[lane + it * 32];
        }

        const uint32_t WS[4] = {SW1, SW2, SW3, SW4};
        #pragma unroll
        for (int l = 0; l < 4; l++) {
            #pragma unroll
            for (int j = 0; j < 8; j++) {
                A[j][0] = relu_pack(C[2 * j][0],     C[2 * j][1]);
                A[j][1] = relu_pack(C[2 * j][2],     C[2 * j][3]);
                A[j][2] = relu_pack(C[2 * j + 1][0], C[2 * j + 1][1]);
                A[j][3] = relu_pack(C[2 * j + 1][2], C[2 * j + 1][3]);
            }
            const uint32_t wb = sb + WS[l];
            #pragma unroll
            for (int j = 0; j < 8; j++) {
                uint32_t B[4];
                ldsm_x4t(B, wb + joff[j]);
                mma16816_z(C[2 * j],     A[0], B[0], B[1]);
                mma16816_z(C[2 * j + 1], A[0], B[2], B[3]);
            }
            #pragma unroll
            for (int kb = 1; kb < 8; kb++)
                #pragma unroll
                for (int j = 0; j < 8; j++) {
                    uint32_t B[4];
                    ldsm_x4t(B, wb + kb * 4096 + joff[j]);
                    mma16816(C[2 * j],     A[kb], B[0], B[1]);
                    mma16816(C[2 * j + 1], A[kb], B[2], B[3]);
                }
            if (l == 0 && pf) {
                #pragma unroll
                for (int it = 0; it < 4; it++) {
                    int idx = lane + it * 32;
                    int r = idx >> 4, c4 = idx & 15;
                    __half2 h0 = __floats2half2_rn(vb[it].x, vb[it].y);
                    __half2 h1 = __floats2half2_rn(vb[it].z, vb[it].w);
                    uint2 p = make_uint2(*(uint32_t*)&h0, *(uint32_t*)&h1);
                    *(uint2*)(smem + xsts_row + r * XSTR + c4 * 8) = p;
                }
                #pragma unroll
                for (int it = 0; it < 4; it++) vb[it] = xgn[lane + (it + 4) * 32];
            }
            if (l == 1 && pf) {
                #pragma unroll
                for (int it = 0; it < 4; it++) {
                    int idx = lane + (it + 4) * 32;
                    int r = idx >> 4, c4 = idx & 15;
                    __half2 h0 = __floats2half2_rn(vb[it].x, vb[it].y);
                    __half2 h1 = __floats2half2_rn(vb[it].z, vb[it].w);
                    uint2 p = make_uint2(*(uint32_t*)&h0, *(uint32_t*)&h1);
                    *(uint2*)(smem + xsts_row + r * XSTR + c4 * 8) = p;
                }
            }
        }

        #pragma unroll
        for (int j = 0; j < 8; j++) {
            A[j][0] = relu_pack(C[2 * j][0],     C[2 * j][1]);
            A[j][1] = relu_pack(C[2 * j][2],     C[2 * j][3]);
            A[j][2] = relu_pack(C[2 * j + 1][0], C[2 * j + 1][1]);
            A[j][3] = relu_pack(C[2 * j + 1][2], C[2 * j + 1][3]);
        }
        float C5[2][4];
        {
            uint32_t B[4];
            ldsm_x4t(B, w5a);
            mma16816_z(C5[0], A[0], B[0], B[1]);
            mma16816_z(C5[1], A[0], B[2], B[3]);
        }
        #pragma unroll
        for (int kb = 1; kb < 8; kb++) {
            uint32_t B[4];
            ldsm_x4t(B, w5a + kb * 768);
            mma16816(C5[0], A[kb], B[0], B[1]);
            mma16816(C5[1], A[kb], B[2], B[3]);
        }

        const size_t g0 = ((size_t)t * MTILE + 16 * wid + row0) * DIMO;
        const size_t g1 = g0 + 8 * DIMO;
        float2 v;
        v.x = C5[0][0] + bz0; v.y = C5[0][1] + bz1;
        *(float2*)(out + g0 + col0) = v;
        v.x = C5[1][0] + bz2; v.y = C5[1][1] + bz3;
        *(float2*)(out + g0 + 8 + col0) = v;
        v.x = C5[0][2] + bz0; v.y = C5[0][3] + bz1;
        *(float2*)(out + g1 + col0) = v;
        v.x = C5[1][2] + bz2; v.y = C5[1][3] + bz3;
        *(float2*)(out + g1 + 8 + col0) = v;
    }
}

static CUstream _pick_stream() {
    cudaStreamCaptureStatus s = cudaStreamCaptureStatusNone;
    if (cudaStreamIsCapturing((cudaStream_t)0x2, &s) == cudaSuccess &&
        s == cudaStreamCaptureStatusActive)
        return (CUstream)0x2;
    s = cudaStreamCaptureStatusNone;
    if (cudaStreamIsCapturing((cudaStream_t)0x1, &s) == cudaSuccess &&
        s == cudaStreamCaptureStatusActive)
        return (CUstream)0x1;
#ifdef CUDA_API_PER_THREAD_DEFAULT_STREAM
    return (CUstream)0x2;
#else
    return (CUstream)0x1;
#endif
}

extern "C" void kernel_launch(void* const* d_in, const int* in_sizes, int n_in,
                              void* d_out, int out_size) {
    const float* x    = (const float*)d_in[0];
    const float* W0   = (const float*)d_in[1];
    const float* W1   = (const float*)d_in[2];
    const float* W2   = (const float*)d_in[3];
    const float* W3   = (const float*)d_in[4];
    const float* W4   = (const float*)d_in[5];
    const float* W5   = (const float*)d_in[6];
    const float* bias = (const float*)d_in[7];
    float* out = (float*)d_out;

    if (g_tc_ok && g_tc_fn && p_cuLaunchKernel) {
        int grid = g_sm, ntiles = TC_NTILES, probe = 0;
        void* params[12] = {(void*)&x, (void*)&W0, (void*)&W1, (void*)&W2,
                            (void*)&W3, (void*)&W4, (void*)&W5, (void*)&bias,
                            (void*)&out, (void*)&grid, (void*)&ntiles,
                            (void*)&probe};
        CUresult r = p_cuLaunchKernel(g_tc_fn, (unsigned)grid, 1, 1, 512, 1, 1,
                                      TC_SMEM, _pick_stream(), params, nullptr);
        if (r == CUDA_SUCCESS) return;
        fprintf(stderr, "[tc] real launch fail %d — falling back\n", (int)r);
        g_tc_ok = 0;
    }

    cudaFuncSetAttribute(mlp_chain2_kernel,
                         cudaFuncAttributeMaxDynamicSharedMemorySize, SMEM_TOTAL);
    int sm = 148;
    cudaDeviceGetAttribute(&sm, cudaDevAttrMultiProcessorCount, 0);
    int grid = sm < NTILES ? sm : NTILES;
    mlp_chain2_kernel<<<grid, NTHREADS, SMEM_TOTAL>>>(x, W0, W1, W2, W3, W4, W5,
                                                      bias, out);
}